// round 8
// baseline (speedup 1.0000x reference)
#include <cuda_runtime.h>
#include <mma.h>
using namespace nvcuda;

// ---------------- problem constants ----------------
#define NTOT 4096
#define HDIM 128
#define NBAT 64
#define NEDG 131072
#define KSEL 52
#define NKEEP 3328
#define NBLK 296      // 2 CTAs/SM x 148 SMs, all co-resident (launch_bounds(256,2))
#define NTHR 256

// output layout (float32 flat): x_out, A2, batch_out, perm
#define O_A2   425984LL
#define O_BAT  11501568LL
#define O_PERM 11504896LL

// scratch offsets (floats). Tensors needing GEMM operands live as (hi, lo) tf32
// plane pairs: lo plane at hi + tensor_size.
#define WMP    0LL         // combined W1: 4 x 384 x 256 (pair)
#define WKP    786432LL    // Wk: 4 x 128 x 128 (pair)
#define W2P    917504LL    // W2: 4 x 256 x 128 (pair)
#define LWP    1179648LL   // lin_W: 2 x 128 x 128 (pair)
#define XP     1245184LL   // x: 4096 x 128 (pair)
#define TGP    2293760LL   // target_x: 64 x 128 (pair)
#define XQP    2310144LL   // (pair)
#define TMPP   3358720LL   // (pair)
#define AGP    4407296LL   // (pair)
#define XCP    5455872LL   // (pair)
#define H0P    6504448LL   // 2 heads x (4096 x 384 pair), head stride 3145728
#define H1P    12795904LL  // 2 heads x (4096 x 256 pair), head stride 2097152
#define H2O    16990208LL  // fp32 only, 2 heads x 524288
#define AWO    18038784LL
#define CNTO   18300928LL
#define DEGO   18563072LL
#define SO     18567168LL
#define SCOREO 18829312LL
#define PERMO  18833408LL
#define SCRATCH_TOTAL 18836736LL

__device__ float g_scratch[SCRATCH_TOTAL];
__device__ unsigned g_bar[16 * 32];

__device__ __forceinline__ float lrelu(float v) { return v >= 0.f ? v : 0.01f * v; }

__device__ __forceinline__ void fsplit(float v, float& h, float& l) {
    h = wmma::__float_to_tf32(v);
    l = wmma::__float_to_tf32(v - h);
}

// monotonic-ticket grid barrier; gpu-scope fences flush L1D
__device__ __forceinline__ void gsync(int i) {
    __syncthreads();
    if (threadIdx.x == 0) {
        __threadfence();
        unsigned t = atomicAdd(&g_bar[i * 32], 1u);
        unsigned target = (t / NBLK + 1u) * NBLK;
        while ((int)(*(volatile unsigned*)&g_bar[i * 32] - target) < 0) { }
        __threadfence();
    }
    __syncthreads();
}

typedef wmma::fragment<wmma::matrix_a, 16, 16, 8, wmma::precision::tf32, wmma::row_major> FragA;
typedef wmma::fragment<wmma::matrix_b, 16, 16, 8, wmma::precision::tf32, wmma::row_major> FragB;
typedef wmma::fragment<wmma::accumulator, 16, 16, 8, float> FragC;

__device__ __forceinline__ void mma3(FragC& d, const FragA& ah, const FragA& al,
                                     const FragB& bh, const FragB& bl) {
    wmma::mma_sync(d, al, bh, d);
    wmma::mma_sync(d, ah, bl, d);
    wmma::mma_sync(d, ah, bh, d);
}

// ---------------- 3xTF32 GEMM tile (64x64), operands are pre-split planes ----------
// mode 1: leaky -> fp32 O       mode 2: leaky -> split -> (O, Olo)
// mode 3: h0 epilogue           mode 5: dual-W x_c epilogue
__device__ void dev_gemm(const float* __restrict__ Ah, const float* __restrict__ Al, int K,
                         const float* __restrict__ Wh, const float* __restrict__ Wl, int MO,
                         float* __restrict__ O, float* __restrict__ Olo,
                         int mode, int m0, int n0,
                         const float* __restrict__ q1, const float* __restrict__ q2, int qtar,
                         const float* __restrict__ W2h, const float* __restrict__ W2l,
                         const float* __restrict__ xorig, float* sm) {
    float* Cs = sm;   // [64][68]
    int tid = threadIdx.x;
    int warp = tid >> 5, wr = warp >> 1, wc = warp & 1;
    FragC acc[2], acc2[2];
    #pragma unroll
    for (int t = 0; t < 2; t++) wmma::fill_fragment(acc[t], 0.f);
    if (mode == 5) {
        #pragma unroll
        for (int t = 0; t < 2; t++) wmma::fill_fragment(acc2[t], 0.f);
    }

    const float* arh = Ah + (size_t)(m0 + wr * 16) * K;
    const float* arl = Al + (size_t)(m0 + wr * 16) * K;
    for (int k = 0; k < K; k += 8) {
        FragA ah, al;
        wmma::load_matrix_sync(ah, arh + k, K);
        wmma::load_matrix_sync(al, arl + k, K);
        #pragma unroll
        for (int t = 0; t < 2; t++) {
            FragB bh, bl;
            wmma::load_matrix_sync(bh, Wh + (size_t)k * MO + n0 + wc * 32 + t * 16, MO);
            wmma::load_matrix_sync(bl, Wl + (size_t)k * MO + n0 + wc * 32 + t * 16, MO);
            mma3(acc[t], ah, al, bh, bl);
            if (mode == 5) {
                FragB ch, cl;
                wmma::load_matrix_sync(ch, W2h + (size_t)k * MO + n0 + wc * 32 + t * 16, MO);
                wmma::load_matrix_sync(cl, W2l + (size_t)k * MO + n0 + wc * 32 + t * 16, MO);
                mma3(acc2[t], ah, al, ch, cl);
            }
        }
    }

    if (mode == 1) {
        #pragma unroll
        for (int t = 0; t < 2; t++) {
            #pragma unroll
            for (int e = 0; e < acc[t].num_elements; e++) acc[t].x[e] = lrelu(acc[t].x[e]);
            wmma::store_matrix_sync(O + (size_t)(m0 + wr * 16) * MO + n0 + wc * 32 + t * 16,
                                    acc[t], MO, wmma::mem_row_major);
        }
        return;
    }
    if (mode == 2) {
        #pragma unroll
        for (int t = 0; t < 2; t++) {
            FragC flo;
            #pragma unroll
            for (int e = 0; e < acc[t].num_elements; e++) {
                float v = lrelu(acc[t].x[e]);
                fsplit(v, acc[t].x[e], flo.x[e]);
            }
            size_t off = (size_t)(m0 + wr * 16) * MO + n0 + wc * 32 + t * 16;
            wmma::store_matrix_sync(O + off, acc[t], MO, wmma::mem_row_major);
            wmma::store_matrix_sync(Olo + off, flo, MO, wmma::mem_row_major);
        }
        return;
    }

    // element-addressed epilogues: stage via smem
    #pragma unroll
    for (int t = 0; t < 2; t++)
        wmma::store_matrix_sync(&Cs[(wr * 16) * 68 + wc * 32 + t * 16], acc[t], 68,
                                wmma::mem_row_major);
    __syncthreads();

    int r = tid >> 2, cbase = (tid & 3) * 16;
    int node = m0 + r;
    if (mode == 3) {   // h0 = [a | q | a*q], split planes
        size_t hb = (size_t)node * 384;
        size_t qoff = qtar ? (size_t)(node >> 6) * 128 : (size_t)node * 128;
        #pragma unroll 4
        for (int j = 0; j < 16; j++) {
            int kg = n0 + cbase + j;
            float av = Cs[r * 68 + cbase + j];
            float qh = q1[qoff + kg], ql = q2[qoff + kg];
            float qv = qh + ql;
            float hh, hl;
            fsplit(av, hh, hl);
            O[hb + kg] = hh;            Olo[hb + kg] = hl;
            O[hb + 128 + kg] = qh;      Olo[hb + 128 + kg] = ql;
            fsplit(av * qv, hh, hl);
            O[hb + 256 + kg] = hh;      Olo[hb + 256 + kg] = hl;
        }
    } else {           // mode 5: x_c = 0.5*(lrelu(x+t0)+lrelu(x+t1)), split planes
        float t0v[16];
        #pragma unroll
        for (int j = 0; j < 16; j++) t0v[j] = Cs[r * 68 + cbase + j];
        __syncthreads();
        #pragma unroll
        for (int t = 0; t < 2; t++)
            wmma::store_matrix_sync(&Cs[(wr * 16) * 68 + wc * 32 + t * 16], acc2[t], 68,
                                    wmma::mem_row_major);
        __syncthreads();
        const float* xrow = xorig + (size_t)node * 128;
        #pragma unroll 4
        for (int j = 0; j < 16; j++) {
            int kg = n0 + cbase + j;
            float xv = xrow[kg];
            float v = 0.5f * (lrelu(xv + t0v[j]) + lrelu(xv + Cs[r * 68 + cbase + j]));
            float hh, hl;
            fsplit(v, hh, hl);
            O[(size_t)node * 128 + kg] = hh;
            Olo[(size_t)node * 128 + kg] = hl;
        }
    }
    __syncthreads();
}

// ---------------- per-batch out = M^T @ v (64x64 @ 64x128), v pre-split ------------
__device__ void dev_bgemmT(const float* __restrict__ Mb,
                           const float* __restrict__ vh, const float* __restrict__ vl,
                           float* __restrict__ oh, float* __restrict__ ol, float* sm) {
    float* MsTh = sm;          // [64][68]
    float* MsTl = sm + 4352;   // [64][68]
    int tid = threadIdx.x;
    for (int i = tid; i < 4096; i += NTHR) {
        float hh, hl;
        fsplit(Mb[i], hh, hl);
        MsTh[(i & 63) * 68 + (i >> 6)] = hh;   // transposed
        MsTl[(i & 63) * 68 + (i >> 6)] = hl;
    }
    __syncthreads();
    int warp = tid >> 5, wr = warp >> 2, wc = warp & 3;
    FragC acc[2][2];
    #pragma unroll
    for (int i = 0; i < 2; i++)
        #pragma unroll
        for (int j = 0; j < 2; j++) wmma::fill_fragment(acc[i][j], 0.f);
    for (int k0 = 0; k0 < 64; k0 += 8) {
        FragA ah[2], al[2];
        #pragma unroll
        for (int i = 0; i < 2; i++) {
            wmma::load_matrix_sync(ah[i], &MsTh[(wr * 32 + i * 16) * 68 + k0], 68);
            wmma::load_matrix_sync(al[i], &MsTl[(wr * 32 + i * 16) * 68 + k0], 68);
        }
        #pragma unroll
        for (int j = 0; j < 2; j++) {
            FragB bh, bl;
            wmma::load_matrix_sync(bh, vh + (size_t)k0 * 128 + wc * 32 + j * 16, 128);
            wmma::load_matrix_sync(bl, vl + (size_t)k0 * 128 + wc * 32 + j * 16, 128);
            #pragma unroll
            for (int i = 0; i < 2; i++) mma3(acc[i][j], ah[i], al[i], bh, bl);
        }
    }
    #pragma unroll
    for (int i = 0; i < 2; i++)
        #pragma unroll
        for (int j = 0; j < 2; j++) {
            FragC flo;
            #pragma unroll
            for (int e = 0; e < acc[i][j].num_elements; e++)
                fsplit(acc[i][j].x[e], acc[i][j].x[e], flo.x[e]);
            size_t off = (size_t)(wr * 32 + i * 16) * 128 + wc * 32 + j * 16;
            wmma::store_matrix_sync(oh + off, acc[i][j], 128, wmma::mem_row_major);
            wmma::store_matrix_sync(ol + off, flo, 128, wmma::mem_row_major);
        }
    __syncthreads();
}

// ---------------- W3 dot + leaky + per-batch softmax (64 rows) ----------------
__device__ float fsm_dev(const float* __restrict__ h2b, const float* __restrict__ W3h,
                         float* red) {
    int t = threadIdx.x;
    float v = 0.f;
    if (t < 64) {
        const float* h = h2b + (size_t)t * 128;
        float dot = 0.f;
        #pragma unroll 8
        for (int k = 0; k < 128; k++) dot += h[k] * W3h[k];
        v = lrelu(dot);
        red[t] = v;
    }
    __syncthreads();
    for (int off = 32; off > 0; off >>= 1) {
        if (t < off) red[t] = fmaxf(red[t], red[t + off]);
        __syncthreads();
    }
    float m = red[0];
    __syncthreads();
    float e = 0.f;
    if (t < 64) { e = expf(v - m); red[t] = e; }
    __syncthreads();
    for (int off = 32; off > 0; off >>= 1) {
        if (t < off) red[t] += red[t + off];
        __syncthreads();
    }
    float r = (t < 64) ? e / red[0] : 0.f;
    __syncthreads();
    return r;
}

// ---------------- attention pair (2 heads), 3 GEMM phases + 3 barriers -------------
__device__ void attn_pair(const float* __restrict__ kvh, const float* __restrict__ kvl,
                          const float* __restrict__ qh, const float* __restrict__ ql,
                          int khead, float* sc, float* sm, int bar0) {
    int bid = blockIdx.x;
    for (int tix = bid; tix < 256; tix += NBLK) {       // gemm1 + fused h0 build
        int head = tix >> 7, rem = tix & 127;
        int m0 = (rem & 63) * 64, n0 = (rem >> 6) * 64;
        const float* wkh = sc + WKP + (size_t)(khead + head) * 16384;
        float* h0h = sc + H0P + (size_t)head * 3145728;
        dev_gemm(kvh, kvl, 128, wkh, wkh + 65536, 128,
                 h0h, h0h + 1572864, 3, m0, n0,
                 head ? sc + TGP : qh, head ? sc + TGP + 8192 : ql, head ? 1 : 0,
                 nullptr, nullptr, nullptr, sm);
    }
    gsync(bar0);
    for (int tix = bid; tix < 512; tix += NBLK) {       // h1 = leaky(h0 @ Wm)
        int head = tix >> 8, rem = tix & 255;
        int m0 = (rem & 63) * 64, n0 = (rem >> 6) * 64;
        const float* h0h = sc + H0P + (size_t)head * 3145728;
        const float* wmh = sc + WMP + (size_t)(khead + head) * 98304;
        float* h1h = sc + H1P + (size_t)head * 2097152;
        dev_gemm(h0h, h0h + 1572864, 384, wmh, wmh + 393216, 256,
                 h1h, h1h + 1048576, 2, m0, n0,
                 nullptr, nullptr, 0, nullptr, nullptr, nullptr, sm);
    }
    gsync(bar0 + 1);
    for (int tix = bid; tix < 256; tix += NBLK) {       // h2 = leaky(h1 @ W2)
        int head = tix >> 7, rem = tix & 127;
        int m0 = (rem & 63) * 64, n0 = (rem >> 6) * 64;
        const float* h1h = sc + H1P + (size_t)head * 2097152;
        const float* w2h = sc + W2P + (size_t)(khead + head) * 32768;
        dev_gemm(h1h, h1h + 1048576, 256, w2h, w2h + 131072, 128,
                 sc + H2O + (size_t)head * 524288, nullptr, 1, m0, n0,
                 nullptr, nullptr, 0, nullptr, nullptr, nullptr, sm);
    }
    gsync(bar0 + 2);
}

// ==================== megakernel ====================
__global__ void __launch_bounds__(NTHR, 2)
mega(const float* __restrict__ x, const int* __restrict__ ei,
     const float* __restrict__ ew, const float* __restrict__ tgt,
     const float* __restrict__ Wk, const float* __restrict__ W1,
     const float* __restrict__ W2, const float* __restrict__ W3,
     const float* __restrict__ lW, float* __restrict__ out) {
    __shared__ __align__(16) float sm[12288];   // 48 KB
    float* sc = g_scratch;
    int bid = blockIdx.x, tid = threadIdx.x;
    int gth = bid * NTHR + tid;
    const int GSTR = NBLK * NTHR;

    // ---- B0: build all tf32 hi/lo planes; zero Aw/cnt/deg + A2 ----
    for (int i = gth; i < 4 * 384 * 256; i += GSTR) {   // Wm = [Wa+Wc; Wb-Wc; Wd]
        int c = i & 255, r = (i >> 8) % 384, h = i / (384 * 256);
        const float* Wh = W1 + (size_t)h * 512 * 256;
        float v;
        if (r < 128)      v = Wh[r * 256 + c] + Wh[(256 + r) * 256 + c];
        else if (r < 256) v = Wh[r * 256 + c] - Wh[(r + 128) * 256 + c];
        else              v = Wh[(r + 128) * 256 + c];
        fsplit(v, sc[WMP + i], sc[WMP + 393216 + i]);
    }
    for (int i = gth; i < 4 * 16384; i += GSTR)  fsplit(Wk[i], sc[WKP + i], sc[WKP + 65536 + i]);
    for (int i = gth; i < 4 * 32768; i += GSTR)  fsplit(W2[i], sc[W2P + i], sc[W2P + 131072 + i]);
    for (int i = gth; i < 2 * 16384; i += GSTR)  fsplit(lW[i], sc[LWP + i], sc[LWP + 32768 + i]);
    for (int i = gth; i < NTOT * 128; i += GSTR) fsplit(x[i],  sc[XP + i],  sc[XP + 524288 + i]);
    for (int i = gth; i < NBAT * 128; i += GSTR) fsplit(tgt[i], sc[TGP + i], sc[TGP + 8192 + i]);
    {
        float4 z = make_float4(0.f, 0.f, 0.f, 0.f);
        float4* p = (float4*)(sc + AWO);
        for (int i = gth; i < 528384 / 4; i += GSTR) p[i] = z;
        float4* p2 = (float4*)(out + O_A2);
        for (int i = gth; i < (NKEEP * NKEEP) / 4; i += GSTR) p2[i] = z;
    }
    gsync(0);

    // ---- B1: degree ----
    for (int e = gth; e < NEDG + NTOT; e += GSTR) {
        if (e < NEDG) atomicAdd(&sc[DEGO + ei[NEDG + e]], ew[e]);
        else          atomicAdd(&sc[DEGO + e - NEDG], 1.0f);
    }
    gsync(1);

    // ---- B2: dense adjacency with inline dinv ----
    for (int e = gth; e < NEDG + NTOT; e += GSTR) {
        int r, c; float wv;
        if (e < NEDG) { r = ei[e]; c = ei[NEDG + e]; wv = ew[e]; }
        else          { r = c = e - NEDG; wv = 1.f; }
        float dr = sc[DEGO + r], dc = sc[DEGO + c];
        float ir = dr > 0.f ? rsqrtf(fmaxf(dr, 1e-12f)) : 0.f;
        float ic = dc > 0.f ? rsqrtf(fmaxf(dc, 1e-12f)) : 0.f;
        int o = ((r >> 6) << 12) + ((r & 63) << 6) + (c & 63);
        atomicAdd(&sc[AWO + o], ir * wv * ic);
        atomicAdd(&sc[CNTO + o], 1.f);
    }
    gsync(2);

    // ---- B3/B4: x_q = hop(hop(x)) ----
    if (bid < NBAT)
        dev_bgemmT(sc + AWO + (size_t)bid * 4096,
                   sc + XP + (size_t)bid * 8192, sc + XP + 524288 + (size_t)bid * 8192,
                   sc + TMPP + (size_t)bid * 8192, sc + TMPP + 524288 + (size_t)bid * 8192, sm);
    gsync(3);
    if (bid < NBAT)
        dev_bgemmT(sc + AWO + (size_t)bid * 4096,
                   sc + TMPP + (size_t)bid * 8192, sc + TMPP + 524288 + (size_t)bid * 8192,
                   sc + XQP + (size_t)bid * 8192, sc + XQP + 524288 + (size_t)bid * 8192, sm);
    gsync(4);

    // ---- B5-B7: f1 = att(x, x_q), f2 = att(x, qt) ----
    attn_pair(sc + XP, sc + XP + 524288, sc + XQP, sc + XQP + 524288, 0, sc, sm, 5);

    // ---- B8: per-batch fsm(f1), fsm(f2), edge-softmax S, agg = S^T x ----
    if (bid < NBAT) {
        float* red = sm;
        float* f1s = sm + 64;
        float* f2s = sm + 128;
        float f1v = fsm_dev(sc + H2O + (size_t)bid * 8192, W3, red);
        float f2v = fsm_dev(sc + H2O + 524288 + (size_t)bid * 8192, W3 + 128, red);
        if (tid < 64) { f1s[tid] = f1v; f2s[tid] = f2v; }
        __syncthreads();
        if (tid < 64) {
            int c = tid;
            float f1c = f1s[c];
            const float* Cb = sc + CNTO + (size_t)bid * 4096;
            float* Sb = sc + SO + (size_t)bid * 4096;
            float m = -1e30f;
            for (int r = 0; r < 64; r++) m = fmaxf(m, lrelu(f1c + f2s[r]));
            float d = 0.f;
            for (int r = 0; r < 64; r++) {
                float val = lrelu(f1c + f2s[r]);
                float e = Cb[r * 64 + c] * expf(val - m);
                Sb[r * 64 + c] = e; d += e;
            }
            float inv = 1.f / d;
            for (int r = 0; r < 64; r++) Sb[r * 64 + c] *= inv;
        }
        __syncthreads();
        dev_bgemmT(sc + SO + (size_t)bid * 4096,
                   sc + XP + (size_t)bid * 8192, sc + XP + 524288 + (size_t)bid * 8192,
                   sc + AGP + (size_t)bid * 8192, sc + AGP + 524288 + (size_t)bid * 8192,
                   sm + 256);
    }
    gsync(8);

    // ---- B9: x_c = 0.5*(lrelu(x+agg@W0)+lrelu(x+agg@W1)) ----
    for (int tix = bid; tix < 128; tix += NBLK) {
        int m0 = (tix & 63) * 64, n0 = (tix >> 6) * 64;
        dev_gemm(sc + AGP, sc + AGP + 524288, 128,
                 sc + LWP, sc + LWP + 32768, 128,
                 sc + XCP, sc + XCP + 524288, 5, m0, n0,
                 nullptr, nullptr, 0,
                 sc + LWP + 16384, sc + LWP + 49152, x, sm);
    }
    gsync(9);

    // ---- B10/B11: x_q2 = hop(hop(x_c)) ----
    if (bid < NBAT)
        dev_bgemmT(sc + AWO + (size_t)bid * 4096,
                   sc + XCP + (size_t)bid * 8192, sc + XCP + 524288 + (size_t)bid * 8192,
                   sc + TMPP + (size_t)bid * 8192, sc + TMPP + 524288 + (size_t)bid * 8192, sm);
    gsync(10);
    if (bid < NBAT)
        dev_bgemmT(sc + AWO + (size_t)bid * 4096,
                   sc + TMPP + (size_t)bid * 8192, sc + TMPP + 524288 + (size_t)bid * 8192,
                   sc + XQP + (size_t)bid * 8192, sc + XQP + 524288 + (size_t)bid * 8192, sm);
    gsync(11);

    // ---- B12-B14: g1 = att(x_c, x_q2), g2 = att(x_c, qt) ----
    attn_pair(sc + XCP, sc + XCP + 524288, sc + XQP, sc + XQP + 524288, 2, sc, sm, 12);

    // ---- B15: fsm(g1), fsm(g2), score softmax, rank-based top-k ----
    if (bid < NBAT) {
        float* red = sm;
        float* ss = sm + 64;
        float g1v = fsm_dev(sc + H2O + (size_t)bid * 8192, W3 + 256, red);
        float g2v = fsm_dev(sc + H2O + 524288 + (size_t)bid * 8192, W3 + 384, red);
        float v = g1v + g2v;
        if (tid < 64) red[tid] = v;
        __syncthreads();
        for (int off = 32; off > 0; off >>= 1) {
            if (tid < off) red[tid] = fmaxf(red[tid], red[tid + off]);
            __syncthreads();
        }
        float m = red[0];
        __syncthreads();
        float e = 0.f;
        if (tid < 64) { e = expf(v - m); red[tid] = e; }
        __syncthreads();
        for (int off = 32; off > 0; off >>= 1) {
            if (tid < off) red[tid] += red[tid + off];
            __syncthreads();
        }
        float si = (tid < 64) ? e / red[0] : 0.f;
        __syncthreads();
        if (tid < 64) ss[tid] = si;
        __syncthreads();
        if (tid < 64) {
            int rank = 0;
            for (int j = 0; j < 64; j++) {
                float sj = ss[j];
                rank += (sj > si) || (sj == si && j < tid);
            }
            sc[SCOREO + bid * 64 + tid] = si;
            if (rank < KSEL) ((int*)(sc + PERMO))[bid * KSEL + rank] = tid;
        }
    }
    gsync(15);

    // ---- B16: outputs — blocks 0-63: A2 blocks; 64-295: x_out/batch/perm ----
    if (bid < NBAT) {
        float* Aws = sm;           // [64][65]
        float* Sp  = sm + 4160;    // [64][53]
        float* Ms  = sm + 7552;    // [64][53]
        int*   idx = (int*)(sm + 10944);
        const int* perm = (const int*)(sc + PERMO);
        const float* Ab = sc + AWO + (size_t)bid * 4096;
        for (int i = tid; i < 4096; i += NTHR) Aws[(i >> 6) * 65 + (i & 63)] = Ab[i];
        if (tid < KSEL) idx[tid] = perm[bid * KSEL + tid];
        __syncthreads();
        const float* Sb = sc + SO + (size_t)bid * 4096;
        for (int i = tid; i < 64 * KSEL; i += NTHR) {
            int r = i / KSEL, j = i % KSEL;
            Sp[r * 53 + j] = Sb[r * 64 + idx[j]];
        }
        __syncthreads();
        for (int i = tid; i < 64 * KSEL; i += NTHR) {
            int r = i / KSEL, j = i % KSEL;
            float acc = 0.f;
            #pragma unroll 8
            for (int c = 0; c < 64; c++) acc += Aws[r * 65 + c] * Sp[c * 53 + j];
            Ms[r * 53 + j] = acc;
        }
        __syncthreads();
        for (int i = tid; i < KSEL * KSEL; i += NTHR) {
            int ii = i / KSEL, j = i % KSEL;
            float v;
            if (ii == j) v = 1.f;
            else {
                v = 0.f;
                #pragma unroll 8
                for (int r = 0; r < 64; r++) v += Sp[r * 53 + ii] * Ms[r * 53 + j];
            }
            long long gi = (long long)bid * KSEL + ii;
            out[O_A2 + gi * NKEEP + bid * KSEL + j] = v;
        }
    } else {
        const int* perm = (const int*)(sc + PERMO);
        for (int t = (bid - NBAT) * NTHR + tid; t < NKEEP * HDIM; t += (NBLK - NBAT) * NTHR) {
            int j = t >> 7, k = t & 127;
            int b = j / KSEL;
            int pg = b * 64 + perm[j];
            out[t] = x[(size_t)pg * 128 + k] * sc[SCOREO + pg];
            if (k == 0) {
                out[O_BAT + j]  = (float)b;
                out[O_PERM + j] = (float)pg;
            }
        }
    }
}

extern "C" void kernel_launch(void* const* d_in, const int* in_sizes, int n_in,
                              void* d_out, int out_size) {
    const float* x   = (const float*)d_in[0];
    const int*   ei  = (const int*)d_in[1];
    const float* ew  = (const float*)d_in[2];
    const float* tgt = (const float*)d_in[3];
    const float* Wk  = (const float*)d_in[5];
    const float* W1  = (const float*)d_in[6];
    const float* W2  = (const float*)d_in[7];
    const float* W3  = (const float*)d_in[8];
    const float* lW  = (const float*)d_in[9];
    mega<<<NBLK, NTHR>>>(x, ei, ew, tgt, Wk, W1, W2, W3, lW, (float*)d_out);
}

// round 9
// speedup vs baseline: 1.1359x; 1.1359x over previous
#include <cuda_runtime.h>
#include <mma.h>
using namespace nvcuda;

// ---------------- problem constants ----------------
#define NTOT 4096
#define HDIM 128
#define NBAT 64
#define NEDG 131072
#define KSEL 52
#define NKEEP 3328
#define NBLK 296      // 2 CTAs/SM x 148 SMs, all co-resident
#define NTHR 256

// output layout (float32 flat): x_out, A2, batch_out, perm
#define O_A2   425984LL
#define O_BAT  11501568LL
#define O_PERM 11504896LL

// scratch offsets (floats); pair tensors store hi plane then lo plane
#define WMP    0LL         // combined W1: 4 x 384 x 256 pair
#define WKP    786432LL    // Wk pair
#define W2P    917504LL    // W2 pair
#define LWP    1179648LL   // lin_W pair
#define XP     1245184LL   // x pair (lo +524288)
#define TGP    2293760LL   // target pair (lo +8192)
#define XQP    2310144LL   // pair
#define AGP    3358720LL   // pair
#define XCP    4407296LL   // pair
#define M2P    5455872LL   // per-batch M2 = Aw^T Aw^T, pair (lo +262144)
#define H0P    5980160LL   // 2 heads x (4096x384 pair), head stride 3145728, lo +1572864
#define H1P    12271616LL  // 2 heads x (4096x256 pair), head stride 2097152, lo +1048576
#define H2O    16465920LL  // fp32, 2 x 524288
#define AWO    17514496LL
#define CNTO   17776640LL
#define DEGO   18038784LL
#define SO     18042880LL
#define SCOREO 18305024LL
#define PERMO  18309120LL
#define SCRATCH_TOTAL 18313216LL

__device__ float g_scratch[SCRATCH_TOTAL];
__device__ unsigned g_bar[16 * 32];

__device__ __forceinline__ float lrelu(float v) { return v >= 0.f ? v : 0.01f * v; }

__device__ __forceinline__ void fsplit(float v, float& h, float& l) {
    h = wmma::__float_to_tf32(v);
    l = wmma::__float_to_tf32(v - h);
}

// monotonic-ticket grid barrier; gpu-scope fences flush L1D
__device__ __forceinline__ void gsync(int i) {
    __syncthreads();
    if (threadIdx.x == 0) {
        __threadfence();
        unsigned t = atomicAdd(&g_bar[i * 32], 1u);
        unsigned target = (t / NBLK + 1u) * NBLK;
        while ((int)(*(volatile unsigned*)&g_bar[i * 32] - target) < 0) { }
        __threadfence();
    }
    __syncthreads();
}

typedef wmma::fragment<wmma::matrix_a, 16, 16, 8, wmma::precision::tf32, wmma::row_major> FragA;
typedef wmma::fragment<wmma::matrix_b, 16, 16, 8, wmma::precision::tf32, wmma::row_major> FragB;
typedef wmma::fragment<wmma::accumulator, 16, 16, 8, float> FragC;

__device__ __forceinline__ void mma3(FragC& d, const FragA& ah, const FragA& al,
                                     const FragB& bh, const FragB& bl) {
    wmma::mma_sync(d, al, bh, d);
    wmma::mma_sync(d, ah, bl, d);
    wmma::mma_sync(d, ah, bh, d);
}

// ---------------- 3xTF32 GEMM tile (64x64), smem-staged pre-split operands ---------
// mode 1: leaky->fp32   2: leaky->split pair   3: h0 epilogue   5: dual-W x_c epilogue
#define BK 32
__device__ void dev_gemm(const float* __restrict__ Ah, const float* __restrict__ Al, int K,
                         const float* __restrict__ Wh, const float* __restrict__ Wl, int MO,
                         float* __restrict__ O, float* __restrict__ Olo,
                         int mode, int m0, int n0,
                         const float* __restrict__ q1, const float* __restrict__ q2, int qtar,
                         const float* __restrict__ W2h, const float* __restrict__ W2l,
                         const float* __restrict__ xorig, float* sm) {
    float* Ash = sm;            // [64][36]
    float* Asl = sm + 2304;
    float* Wsh = sm + 4608;     // [32][68]
    float* Wsl = sm + 6784;
    float* Cs  = sm + 4608;     // reused after k-loop (modes 3/5)
    int tid = threadIdx.x;
    int warp = tid >> 5, wr = warp >> 1, wc = warp & 1;
    FragC acc[2], acc2[2];
    #pragma unroll
    for (int t = 0; t < 2; t++) wmma::fill_fragment(acc[t], 0.f);
    if (mode == 5) {
        #pragma unroll
        for (int t = 0; t < 2; t++) wmma::fill_fragment(acc2[t], 0.f);
    }

    for (int k0 = 0; k0 < K; k0 += BK) {
        #pragma unroll
        for (int s = 0; s < 2; s++) {
            int i = tid + s * 256;
            int r = i >> 3, c = (i & 7) * 4;
            *(float4*)&Ash[r * 36 + c] = *(const float4*)(Ah + (size_t)(m0 + r) * K + k0 + c);
            *(float4*)&Asl[r * 36 + c] = *(const float4*)(Al + (size_t)(m0 + r) * K + k0 + c);
        }
        if (mode != 5) {
            #pragma unroll
            for (int s = 0; s < 2; s++) {
                int i = tid + s * 256;
                int r = i >> 4, c = (i & 15) * 4;
                *(float4*)&Wsh[r * 68 + c] = *(const float4*)(Wh + (size_t)(k0 + r) * MO + n0 + c);
                *(float4*)&Wsl[r * 68 + c] = *(const float4*)(Wl + (size_t)(k0 + r) * MO + n0 + c);
            }
        }
        __syncthreads();
        #pragma unroll
        for (int kk = 0; kk < BK; kk += 8) {
            FragA ah, al;
            wmma::load_matrix_sync(ah, &Ash[(wr * 16) * 36 + kk], 36);
            wmma::load_matrix_sync(al, &Asl[(wr * 16) * 36 + kk], 36);
            #pragma unroll
            for (int t = 0; t < 2; t++) {
                FragB bh, bl;
                if (mode != 5) {
                    wmma::load_matrix_sync(bh, &Wsh[kk * 68 + wc * 32 + t * 16], 68);
                    wmma::load_matrix_sync(bl, &Wsl[kk * 68 + wc * 32 + t * 16], 68);
                } else {
                    wmma::load_matrix_sync(bh, Wh + (size_t)(k0 + kk) * MO + n0 + wc * 32 + t * 16, MO);
                    wmma::load_matrix_sync(bl, Wl + (size_t)(k0 + kk) * MO + n0 + wc * 32 + t * 16, MO);
                }
                mma3(acc[t], ah, al, bh, bl);
                if (mode == 5) {
                    FragB ch, cl;
                    wmma::load_matrix_sync(ch, W2h + (size_t)(k0 + kk) * MO + n0 + wc * 32 + t * 16, MO);
                    wmma::load_matrix_sync(cl, W2l + (size_t)(k0 + kk) * MO + n0 + wc * 32 + t * 16, MO);
                    mma3(acc2[t], ah, al, ch, cl);
                }
            }
        }
        __syncthreads();
    }

    if (mode == 1) {
        #pragma unroll
        for (int t = 0; t < 2; t++) {
            #pragma unroll
            for (int e = 0; e < acc[t].num_elements; e++) acc[t].x[e] = lrelu(acc[t].x[e]);
            wmma::store_matrix_sync(O + (size_t)(m0 + wr * 16) * MO + n0 + wc * 32 + t * 16,
                                    acc[t], MO, wmma::mem_row_major);
        }
        return;
    }
    if (mode == 2) {
        #pragma unroll
        for (int t = 0; t < 2; t++) {
            FragC flo;
            #pragma unroll
            for (int e = 0; e < acc[t].num_elements; e++) {
                float v = lrelu(acc[t].x[e]);
                fsplit(v, acc[t].x[e], flo.x[e]);
            }
            size_t off = (size_t)(m0 + wr * 16) * MO + n0 + wc * 32 + t * 16;
            wmma::store_matrix_sync(O + off, acc[t], MO, wmma::mem_row_major);
            wmma::store_matrix_sync(Olo + off, flo, MO, wmma::mem_row_major);
        }
        return;
    }

    // element-addressed epilogues via smem
    #pragma unroll
    for (int t = 0; t < 2; t++)
        wmma::store_matrix_sync(&Cs[(wr * 16) * 68 + wc * 32 + t * 16], acc[t], 68,
                                wmma::mem_row_major);
    __syncthreads();

    int r = tid >> 2, cbase = (tid & 3) * 16;
    int node = m0 + r;
    if (mode == 3) {   // h0 = [a | q | a*q] split planes
        size_t hb = (size_t)node * 384;
        size_t qoff = qtar ? (size_t)(node >> 6) * 128 : (size_t)node * 128;
        #pragma unroll 4
        for (int j = 0; j < 16; j++) {
            int kg = n0 + cbase + j;
            float av = Cs[r * 68 + cbase + j];
            float qh = q1[qoff + kg], ql = q2[qoff + kg];
            float qv = qh + ql;
            float hh, hl;
            fsplit(av, hh, hl);
            O[hb + kg] = hh;            Olo[hb + kg] = hl;
            O[hb + 128 + kg] = qh;      Olo[hb + 128 + kg] = ql;
            fsplit(av * qv, hh, hl);
            O[hb + 256 + kg] = hh;      Olo[hb + 256 + kg] = hl;
        }
    } else {           // mode 5: x_c split planes
        float t0v[16];
        #pragma unroll
        for (int j = 0; j < 16; j++) t0v[j] = Cs[r * 68 + cbase + j];
        __syncthreads();
        #pragma unroll
        for (int t = 0; t < 2; t++)
            wmma::store_matrix_sync(&Cs[(wr * 16) * 68 + wc * 32 + t * 16], acc2[t], 68,
                                    wmma::mem_row_major);
        __syncthreads();
        const float* xrow = xorig + (size_t)node * 128;
        #pragma unroll 4
        for (int j = 0; j < 16; j++) {
            int kg = n0 + cbase + j;
            float xv = xrow[kg];
            float v = 0.5f * (lrelu(xv + t0v[j]) + lrelu(xv + Cs[r * 68 + cbase + j]));
            float hh, hl;
            fsplit(v, hh, hl);
            O[(size_t)node * 128 + kg] = hh;
            Olo[(size_t)node * 128 + kg] = hl;
        }
    }
    __syncthreads();
}

// ---------------- M2 = Aw^T @ Aw^T per batch (64x64), split output ----------------
__device__ void dev_m2(const float* __restrict__ Aw, float* __restrict__ Ph,
                       float* __restrict__ Pl, float* sm) {
    float* Th = sm;          // [64][68] = Aw^T hi
    float* Tl = sm + 4352;
    int tid = threadIdx.x;
    for (int i = tid; i < 4096; i += NTHR) {
        float hh, hl;
        fsplit(Aw[i], hh, hl);
        int r = i >> 6, c = i & 63;
        Th[c * 68 + r] = hh; Tl[c * 68 + r] = hl;
    }
    __syncthreads();
    int warp = tid >> 5, wr = warp >> 1, wc = warp & 1;
    FragC acc[2];
    #pragma unroll
    for (int t = 0; t < 2; t++) wmma::fill_fragment(acc[t], 0.f);
    for (int k0 = 0; k0 < 64; k0 += 8) {
        FragA ah, al;
        wmma::load_matrix_sync(ah, &Th[(wr * 16) * 68 + k0], 68);
        wmma::load_matrix_sync(al, &Tl[(wr * 16) * 68 + k0], 68);
        #pragma unroll
        for (int t = 0; t < 2; t++) {
            FragB bh, bl;
            wmma::load_matrix_sync(bh, &Th[k0 * 68 + wc * 32 + t * 16], 68);
            wmma::load_matrix_sync(bl, &Tl[k0 * 68 + wc * 32 + t * 16], 68);
            mma3(acc[t], ah, al, bh, bl);
        }
    }
    #pragma unroll
    for (int t = 0; t < 2; t++) {
        FragC flo;
        #pragma unroll
        for (int e = 0; e < acc[t].num_elements; e++)
            fsplit(acc[t].x[e], acc[t].x[e], flo.x[e]);
        size_t off = (size_t)(wr * 16) * 64 + wc * 32 + t * 16;
        wmma::store_matrix_sync(Ph + off, acc[t], 64, wmma::mem_row_major);
        wmma::store_matrix_sync(Pl + off, flo, 64, wmma::mem_row_major);
    }
    __syncthreads();
}

// ---------------- apply: out = M2 @ v, 64x64 half-tile (n0 = 0 or 64) --------------
__device__ void dev_bapply(const float* __restrict__ Ph, const float* __restrict__ Pl,
                           const float* __restrict__ vh, const float* __restrict__ vl,
                           int n0, float* __restrict__ oh, float* __restrict__ ol,
                           float* sm) {
    float* Psh = sm;      // [64][68]
    float* Psl = sm + 4352;
    int tid = threadIdx.x;
    for (int i = tid; i < 4096; i += NTHR) {
        int r = i >> 6, c = i & 63;
        Psh[r * 68 + c] = Ph[i];
        Psl[r * 68 + c] = Pl[i];
    }
    __syncthreads();
    int warp = tid >> 5, wr = warp >> 1, wc = warp & 1;
    FragC acc[2];
    #pragma unroll
    for (int t = 0; t < 2; t++) wmma::fill_fragment(acc[t], 0.f);
    for (int k0 = 0; k0 < 64; k0 += 8) {
        FragA ah, al;
        wmma::load_matrix_sync(ah, &Psh[(wr * 16) * 68 + k0], 68);
        wmma::load_matrix_sync(al, &Psl[(wr * 16) * 68 + k0], 68);
        #pragma unroll
        for (int t = 0; t < 2; t++) {
            FragB bh, bl;
            wmma::load_matrix_sync(bh, vh + (size_t)k0 * 128 + n0 + wc * 32 + t * 16, 128);
            wmma::load_matrix_sync(bl, vl + (size_t)k0 * 128 + n0 + wc * 32 + t * 16, 128);
            mma3(acc[t], ah, al, bh, bl);
        }
    }
    #pragma unroll
    for (int t = 0; t < 2; t++) {
        FragC flo;
        #pragma unroll
        for (int e = 0; e < acc[t].num_elements; e++)
            fsplit(acc[t].x[e], acc[t].x[e], flo.x[e]);
        size_t off = (size_t)(wr * 16) * 128 + n0 + wc * 32 + t * 16;
        wmma::store_matrix_sync(oh + off, acc[t], 128, wmma::mem_row_major);
        wmma::store_matrix_sync(ol + off, flo, 128, wmma::mem_row_major);
    }
    __syncthreads();
}

// ---------------- agg: out = S^T @ v (S fp32, split inline) ----------------
__device__ void dev_bgemmT(const float* __restrict__ Mb,
                           const float* __restrict__ vh, const float* __restrict__ vl,
                           float* __restrict__ oh, float* __restrict__ ol, float* sm) {
    float* MsTh = sm;          // [64][68]
    float* MsTl = sm + 4352;
    int tid = threadIdx.x;
    for (int i = tid; i < 4096; i += NTHR) {
        float hh, hl;
        fsplit(Mb[i], hh, hl);
        MsTh[(i & 63) * 68 + (i >> 6)] = hh;
        MsTl[(i & 63) * 68 + (i >> 6)] = hl;
    }
    __syncthreads();
    int warp = tid >> 5, wr = warp >> 2, wc = warp & 3;
    FragC acc[2][2];
    #pragma unroll
    for (int i = 0; i < 2; i++)
        #pragma unroll
        for (int j = 0; j < 2; j++) wmma::fill_fragment(acc[i][j], 0.f);
    for (int k0 = 0; k0 < 64; k0 += 8) {
        FragA ah[2], al[2];
        #pragma unroll
        for (int i = 0; i < 2; i++) {
            wmma::load_matrix_sync(ah[i], &MsTh[(wr * 32 + i * 16) * 68 + k0], 68);
            wmma::load_matrix_sync(al[i], &MsTl[(wr * 32 + i * 16) * 68 + k0], 68);
        }
        #pragma unroll
        for (int j = 0; j < 2; j++) {
            FragB bh, bl;
            wmma::load_matrix_sync(bh, vh + (size_t)k0 * 128 + wc * 32 + j * 16, 128);
            wmma::load_matrix_sync(bl, vl + (size_t)k0 * 128 + wc * 32 + j * 16, 128);
            #pragma unroll
            for (int i = 0; i < 2; i++) mma3(acc[i][j], ah[i], al[i], bh, bl);
        }
    }
    #pragma unroll
    for (int i = 0; i < 2; i++)
        #pragma unroll
        for (int j = 0; j < 2; j++) {
            FragC flo;
            #pragma unroll
            for (int e = 0; e < acc[i][j].num_elements; e++)
                fsplit(acc[i][j].x[e], acc[i][j].x[e], flo.x[e]);
            size_t off = (size_t)(wr * 32 + i * 16) * 128 + wc * 32 + j * 16;
            wmma::store_matrix_sync(oh + off, acc[i][j], 128, wmma::mem_row_major);
            wmma::store_matrix_sync(ol + off, flo, 128, wmma::mem_row_major);
        }
    __syncthreads();
}

// ---------------- W3 dot + leaky + per-batch softmax ----------------
__device__ float fsm_dev(const float* __restrict__ h2b, const float* __restrict__ W3h,
                         float* red) {
    int t = threadIdx.x;
    float v = 0.f;
    if (t < 64) {
        const float* h = h2b + (size_t)t * 128;
        float dot = 0.f;
        #pragma unroll 8
        for (int k = 0; k < 128; k++) dot += h[k] * W3h[k];
        v = lrelu(dot);
        red[t] = v;
    }
    __syncthreads();
    for (int off = 32; off > 0; off >>= 1) {
        if (t < off) red[t] = fmaxf(red[t], red[t + off]);
        __syncthreads();
    }
    float m = red[0];
    __syncthreads();
    float e = 0.f;
    if (t < 64) { e = expf(v - m); red[t] = e; }
    __syncthreads();
    for (int off = 32; off > 0; off >>= 1) {
        if (t < off) red[t] += red[t + off];
        __syncthreads();
    }
    float r = (t < 64) ? e / red[0] : 0.f;
    __syncthreads();
    return r;
}

// ---------------- attention pair (2 heads) ----------------
__device__ void attn_pair(const float* __restrict__ kvh, const float* __restrict__ kvl,
                          const float* __restrict__ qh, const float* __restrict__ ql,
                          int khead, float* sc, float* sm, int bar0) {
    int bid = blockIdx.x;
    for (int tix = bid; tix < 256; tix += NBLK) {       // a = kv@Wk, fused h0 build
        int head = tix >> 7, rem = tix & 127;
        int m0 = (rem & 63) * 64, n0 = (rem >> 6) * 64;
        const float* wkh = sc + WKP + (size_t)(khead + head) * 16384;
        float* h0h = sc + H0P + (size_t)head * 3145728;
        dev_gemm(kvh, kvl, 128, wkh, wkh + 65536, 128,
                 h0h, h0h + 1572864, 3, m0, n0,
                 head ? sc + TGP : qh, head ? sc + TGP + 8192 : ql, head ? 1 : 0,
                 nullptr, nullptr, nullptr, sm);
    }
    gsync(bar0);
    for (int tix = bid; tix < 512; tix += NBLK) {       // h1 = leaky(h0 @ Wm)
        int head = tix >> 8, rem = tix & 255;
        int m0 = (rem & 63) * 64, n0 = (rem >> 6) * 64;
        const float* h0h = sc + H0P + (size_t)head * 3145728;
        const float* wmh = sc + WMP + (size_t)(khead + head) * 98304;
        float* h1h = sc + H1P + (size_t)head * 2097152;
        dev_gemm(h0h, h0h + 1572864, 384, wmh, wmh + 393216, 256,
                 h1h, h1h + 1048576, 2, m0, n0,
                 nullptr, nullptr, 0, nullptr, nullptr, nullptr, sm);
    }
    gsync(bar0 + 1);
    for (int tix = bid; tix < 256; tix += NBLK) {       // h2 = leaky(h1 @ W2)
        int head = tix >> 7, rem = tix & 127;
        int m0 = (rem & 63) * 64, n0 = (rem >> 6) * 64;
        const float* h1h = sc + H1P + (size_t)head * 2097152;
        const float* w2h = sc + W2P + (size_t)(khead + head) * 32768;
        dev_gemm(h1h, h1h + 1048576, 256, w2h, w2h + 131072, 128,
                 sc + H2O + (size_t)head * 524288, nullptr, 1, m0, n0,
                 nullptr, nullptr, 0, nullptr, nullptr, nullptr, sm);
    }
    gsync(bar0 + 2);
}

// ==================== megakernel ====================
__global__ void __launch_bounds__(NTHR, 2)
mega(const float* __restrict__ x, const int* __restrict__ ei,
     const float* __restrict__ ew, const float* __restrict__ tgt,
     const float* __restrict__ Wk, const float* __restrict__ W1,
     const float* __restrict__ W2, const float* __restrict__ W3,
     const float* __restrict__ lW, float* __restrict__ out) {
    __shared__ __align__(16) float sm[12288];
    float* sc = g_scratch;
    int bid = blockIdx.x, tid = threadIdx.x;
    int gth = bid * NTHR + tid;
    const int GSTR = NBLK * NTHR;

    // ---- B0: split planes; zero Aw/cnt/deg + A2 ----
    for (int i = gth; i < 4 * 384 * 256; i += GSTR) {   // Wm = [Wa+Wc; Wb-Wc; Wd]
        int c = i & 255, r = (i >> 8) % 384, h = i / (384 * 256);
        const float* Wh = W1 + (size_t)h * 512 * 256;
        float v;
        if (r < 128)      v = Wh[r * 256 + c] + Wh[(256 + r) * 256 + c];
        else if (r < 256) v = Wh[r * 256 + c] - Wh[(r + 128) * 256 + c];
        else              v = Wh[(r + 128) * 256 + c];
        fsplit(v, sc[WMP + i], sc[WMP + 393216 + i]);
    }
    for (int i = gth; i < 4 * 16384; i += GSTR)  fsplit(Wk[i], sc[WKP + i], sc[WKP + 65536 + i]);
    for (int i = gth; i < 4 * 32768; i += GSTR)  fsplit(W2[i], sc[W2P + i], sc[W2P + 131072 + i]);
    for (int i = gth; i < 2 * 16384; i += GSTR)  fsplit(lW[i], sc[LWP + i], sc[LWP + 32768 + i]);
    for (int i = gth; i < NTOT * 128; i += GSTR) fsplit(x[i],  sc[XP + i],  sc[XP + 524288 + i]);
    for (int i = gth; i < NBAT * 128; i += GSTR) fsplit(tgt[i], sc[TGP + i], sc[TGP + 8192 + i]);
    {
        float4 z = make_float4(0.f, 0.f, 0.f, 0.f);
        float4* p = (float4*)(sc + AWO);
        for (int i = gth; i < 528384 / 4; i += GSTR) p[i] = z;
        float4* p2 = (float4*)(out + O_A2);
        for (int i = gth; i < (NKEEP * NKEEP) / 4; i += GSTR) p2[i] = z;
    }
    gsync(0);

    // ---- B1: degree ----
    for (int e = gth; e < NEDG + NTOT; e += GSTR) {
        if (e < NEDG) atomicAdd(&sc[DEGO + ei[NEDG + e]], ew[e]);
        else          atomicAdd(&sc[DEGO + e - NEDG], 1.0f);
    }
    gsync(1);

    // ---- B2: dense adjacency with inline dinv ----
    for (int e = gth; e < NEDG + NTOT; e += GSTR) {
        int r, c; float wv;
        if (e < NEDG) { r = ei[e]; c = ei[NEDG + e]; wv = ew[e]; }
        else          { r = c = e - NEDG; wv = 1.f; }
        float dr = sc[DEGO + r], dc = sc[DEGO + c];
        float ir = dr > 0.f ? rsqrtf(fmaxf(dr, 1e-12f)) : 0.f;
        float ic = dc > 0.f ? rsqrtf(fmaxf(dc, 1e-12f)) : 0.f;
        int o = ((r >> 6) << 12) + ((r & 63) << 6) + (c & 63);
        atomicAdd(&sc[AWO + o], ir * wv * ic);
        atomicAdd(&sc[CNTO + o], 1.f);
    }
    gsync(2);

    // ---- B3: M2 = Aw^T Aw^T per batch ----
    if (bid < NBAT)
        dev_m2(sc + AWO + (size_t)bid * 4096,
               sc + M2P + (size_t)bid * 4096, sc + M2P + 262144 + (size_t)bid * 4096, sm);
    gsync(3);

    // ---- B4: x_q = M2 @ x (128 blocks: batch x col-half) ----
    if (bid < 2 * NBAT) {
        int b = bid >> 1, n0 = (bid & 1) * 64;
        dev_bapply(sc + M2P + (size_t)b * 4096, sc + M2P + 262144 + (size_t)b * 4096,
                   sc + XP + (size_t)b * 8192, sc + XP + 524288 + (size_t)b * 8192, n0,
                   sc + XQP + (size_t)b * 8192, sc + XQP + 524288 + (size_t)b * 8192, sm);
    }
    gsync(4);

    // ---- B5-B7: f1 = att(x, x_q), f2 = att(x, qt) ----
    attn_pair(sc + XP, sc + XP + 524288, sc + XQP, sc + XQP + 524288, 0, sc, sm, 5);

    // ---- B8: fsm(f1), fsm(f2), edge-softmax S, agg = S^T x ----
    if (bid < NBAT) {
        float* red = sm;
        float* f1s = sm + 64;
        float* f2s = sm + 128;
        float f1v = fsm_dev(sc + H2O + (size_t)bid * 8192, W3, red);
        float f2v = fsm_dev(sc + H2O + 524288 + (size_t)bid * 8192, W3 + 128, red);
        if (tid < 64) { f1s[tid] = f1v; f2s[tid] = f2v; }
        __syncthreads();
        if (tid < 64) {
            int c = tid;
            float f1c = f1s[c];
            const float* Cb = sc + CNTO + (size_t)bid * 4096;
            float* Sb = sc + SO + (size_t)bid * 4096;
            float m = -1e30f;
            for (int r = 0; r < 64; r++) m = fmaxf(m, lrelu(f1c + f2s[r]));
            float d = 0.f;
            for (int r = 0; r < 64; r++) {
                float val = lrelu(f1c + f2s[r]);
                float e = Cb[r * 64 + c] * expf(val - m);
                Sb[r * 64 + c] = e; d += e;
            }
            float inv = 1.f / d;
            for (int r = 0; r < 64; r++) Sb[r * 64 + c] *= inv;
        }
        __syncthreads();
        dev_bgemmT(sc + SO + (size_t)bid * 4096,
                   sc + XP + (size_t)bid * 8192, sc + XP + 524288 + (size_t)bid * 8192,
                   sc + AGP + (size_t)bid * 8192, sc + AGP + 524288 + (size_t)bid * 8192,
                   sm + 256);
    }
    gsync(8);

    // ---- B9: x_c = 0.5*(lrelu(x+agg@W0)+lrelu(x+agg@W1)) ----
    for (int tix = bid; tix < 128; tix += NBLK) {
        int m0 = (tix & 63) * 64, n0 = (tix >> 6) * 64;
        dev_gemm(sc + AGP, sc + AGP + 524288, 128,
                 sc + LWP, sc + LWP + 32768, 128,
                 sc + XCP, sc + XCP + 524288, 5, m0, n0,
                 nullptr, nullptr, 0,
                 sc + LWP + 16384, sc + LWP + 49152, x, sm);
    }
    gsync(9);

    // ---- B10: x_q2 = M2 @ x_c ----
    if (bid < 2 * NBAT) {
        int b = bid >> 1, n0 = (bid & 1) * 64;
        dev_bapply(sc + M2P + (size_t)b * 4096, sc + M2P + 262144 + (size_t)b * 4096,
                   sc + XCP + (size_t)b * 8192, sc + XCP + 524288 + (size_t)b * 8192, n0,
                   sc + XQP + (size_t)b * 8192, sc + XQP + 524288 + (size_t)b * 8192, sm);
    }
    gsync(10);

    // ---- B11-B13: g1 = att(x_c, x_q2), g2 = att(x_c, qt) ----
    attn_pair(sc + XCP, sc + XCP + 524288, sc + XQP, sc + XQP + 524288, 2, sc, sm, 11);

    // ---- B14: fsm(g1), fsm(g2), score softmax, rank top-k ----
    if (bid < NBAT) {
        float* red = sm;
        float* ss = sm + 64;
        float g1v = fsm_dev(sc + H2O + (size_t)bid * 8192, W3 + 256, red);
        float g2v = fsm_dev(sc + H2O + 524288 + (size_t)bid * 8192, W3 + 384, red);
        float v = g1v + g2v;
        if (tid < 64) red[tid] = v;
        __syncthreads();
        for (int off = 32; off > 0; off >>= 1) {
            if (tid < off) red[tid] = fmaxf(red[tid], red[tid + off]);
            __syncthreads();
        }
        float m = red[0];
        __syncthreads();
        float e = 0.f;
        if (tid < 64) { e = expf(v - m); red[tid] = e; }
        __syncthreads();
        for (int off = 32; off > 0; off >>= 1) {
            if (tid < off) red[tid] += red[tid + off];
            __syncthreads();
        }
        float si = (tid < 64) ? e / red[0] : 0.f;
        __syncthreads();
        if (tid < 64) ss[tid] = si;
        __syncthreads();
        if (tid < 64) {
            int rank = 0;
            for (int j = 0; j < 64; j++) {
                float sj = ss[j];
                rank += (sj > si) || (sj == si && j < tid);
            }
            sc[SCOREO + bid * 64 + tid] = si;
            if (rank < KSEL) ((int*)(sc + PERMO))[bid * KSEL + rank] = tid;
        }
    }
    gsync(14);

    // ---- B15: outputs ----
    if (bid < NBAT) {
        float* Aws = sm;           // [64][65]
        float* Sp  = sm + 4160;    // [64][53]
        float* Ms  = sm + 7552;    // [64][53]
        int*   idx = (int*)(sm + 10944);
        const int* perm = (const int*)(sc + PERMO);
        const float* Ab = sc + AWO + (size_t)bid * 4096;
        for (int i = tid; i < 4096; i += NTHR) Aws[(i >> 6) * 65 + (i & 63)] = Ab[i];
        if (tid < KSEL) idx[tid] = perm[bid * KSEL + tid];
        __syncthreads();
        const float* Sb = sc + SO + (size_t)bid * 4096;
        for (int i = tid; i < 64 * KSEL; i += NTHR) {
            int r = i / KSEL, j = i % KSEL;
            Sp[r * 53 + j] = Sb[r * 64 + idx[j]];
        }
        __syncthreads();
        for (int i = tid; i < 64 * KSEL; i += NTHR) {
            int r = i / KSEL, j = i % KSEL;
            float acc = 0.f;
            #pragma unroll 8
            for (int c = 0; c < 64; c++) acc += Aws[r * 65 + c] * Sp[c * 53 + j];
            Ms[r * 53 + j] = acc;
        }
        __syncthreads();
        for (int i = tid; i < KSEL * KSEL; i += NTHR) {
            int ii = i / KSEL, j = i % KSEL;
            float v;
            if (ii == j) v = 1.f;
            else {
                v = 0.f;
                #pragma unroll 8
                for (int r = 0; r < 64; r++) v += Sp[r * 53 + ii] * Ms[r * 53 + j];
            }
            long long gi = (long long)bid * KSEL + ii;
            out[O_A2 + gi * NKEEP + bid * KSEL + j] = v;
        }
    } else {
        const int* perm = (const int*)(sc + PERMO);
        for (int t = (bid - NBAT) * NTHR + tid; t < NKEEP * HDIM; t += (NBLK - NBAT) * NTHR) {
            int j = t >> 7, k = t & 127;
            int b = j / KSEL;
            int pg = b * 64 + perm[j];
            out[t] = x[(size_t)pg * 128 + k] * sc[SCOREO + pg];
            if (k == 0) {
                out[O_BAT + j]  = (float)b;
                out[O_PERM + j] = (float)pg;
            }
        }
    }
}

extern "C" void kernel_launch(void* const* d_in, const int* in_sizes, int n_in,
                              void* d_out, int out_size) {
    const float* x   = (const float*)d_in[0];
    const int*   ei  = (const int*)d_in[1];
    const float* ew  = (const float*)d_in[2];
    const float* tgt = (const float*)d_in[3];
    const float* Wk  = (const float*)d_in[5];
    const float* W1  = (const float*)d_in[6];
    const float* W2  = (const float*)d_in[7];
    const float* W3  = (const float*)d_in[8];
    const float* lW  = (const float*)d_in[9];
    mega<<<NBLK, NTHR>>>(x, ei, ew, tgt, Wk, W1, W2, W3, lW, (float*)d_out);
}

// round 13
// speedup vs baseline: 1.1444x; 1.0075x over previous
#include <cuda_runtime.h>
#include <mma.h>
using namespace nvcuda;

// ---------------- problem constants ----------------
#define NTOT 4096
#define HDIM 128
#define NBAT 64
#define NEDG 131072
#define KSEL 52
#define NKEEP 3328
#define NBLK 296      // 2 CTAs/SM x 148 SMs, all co-resident
#define NTHR 256
#define DSMEM_FLOATS 25856     // 103424 bytes dynamic smem

// output layout (float32 flat): x_out, A2, batch_out, perm
#define O_A2   425984LL
#define O_BAT  11501568LL
#define O_PERM 11504896LL

// scratch offsets (floats); pair tensors: hi plane then lo plane
#define WMP    0LL         // combined W1: 4 x 384 x 256 pair (lo +393216)
#define WKP    786432LL    // Wk pair (lo +65536)
#define W2P    917504LL    // W2 pair (lo +131072)
#define LWP    1179648LL   // lin_W pair (lo +32768)
#define XP     1245184LL   // x pair (lo +524288)
#define TGP    2293760LL   // target pair (lo +8192)
#define XQP    2310144LL   // pair
#define AGP    3358720LL   // pair
#define XCP    4407296LL   // pair
#define M2P    5455872LL   // per-batch M2 pair (lo +262144)
#define H0P    5980160LL   // 2 heads x (4096x384 pair), head stride 3145728, lo +1572864
#define H1P    12271616LL  // 2 heads x (4096x256 pair), head stride 2097152, lo +1048576
#define FO     16465920LL  // per-stage f-values, 2 x 4096
#define AWO    16474112LL
#define CNTO   16736256LL
#define DEGO   16998400LL
#define SO     17002496LL
#define SCOREO 17264640LL
#define PERMO  17268736LL
#define SCRATCH_TOTAL 17272832LL

__device__ float g_scratch[SCRATCH_TOTAL];
__device__ unsigned g_bar[16 * 32];

__device__ __forceinline__ float lrelu(float v) { return v >= 0.f ? v : 0.01f * v; }

__device__ __forceinline__ void fsplit(float v, float& h, float& l) {
    h = wmma::__float_to_tf32(v);
    l = wmma::__float_to_tf32(v - h);
}

// monotonic-ticket grid barrier; gpu-scope fences flush L1D
__device__ __forceinline__ void gsync(int i) {
    __syncthreads();
    if (threadIdx.x == 0) {
        __threadfence();
        unsigned t = atomicAdd(&g_bar[i * 32], 1u);
        unsigned target = (t / NBLK + 1u) * NBLK;
        while ((int)(*(volatile unsigned*)&g_bar[i * 32] - target) < 0) { __nanosleep(64); }
        __threadfence();
    }
    __syncthreads();
}

typedef wmma::fragment<wmma::matrix_a, 16, 16, 8, wmma::precision::tf32, wmma::row_major> FragA;
typedef wmma::fragment<wmma::matrix_b, 16, 16, 8, wmma::precision::tf32, wmma::row_major> FragB;
typedef wmma::fragment<wmma::accumulator, 16, 16, 8, float> FragC;

__device__ __forceinline__ void mma3(FragC& d, const FragA& ah, const FragA& al,
                                     const FragB& bh, const FragB& bl) {
    wmma::mma_sync(d, al, bh, d);
    wmma::mma_sync(d, ah, bl, d);
    wmma::mma_sync(d, ah, bh, d);
}

// smem layout inside each GEMM helper (floats):
//   Ash 0, Asl 4352, Wsh 8704, Wsl 13056 (each [64][68]); Cs reuses 8704; H2 Cs at 17408
#define BKB 64

// stage a 64x64 chunk (both planes) of a row-major matrix into [64][68] smem tiles
__device__ __forceinline__ void stage64(const float* __restrict__ Ph,
                                        const float* __restrict__ Pl,
                                        int row0, int col0, int ld,
                                        float* __restrict__ Sh, float* __restrict__ Sl) {
    int tid = threadIdx.x;
    #pragma unroll
    for (int s = 0; s < 4; s++) {
        int i = tid + s * 256;
        int r = i >> 4, c = (i & 15) * 4;
        *(float4*)&Sh[r * 68 + c] = *(const float4*)(Ph + (size_t)(row0 + r) * ld + col0 + c);
        *(float4*)&Sl[r * 68 + c] = *(const float4*)(Pl + (size_t)(row0 + r) * ld + col0 + c);
    }
}

// ---------------- 3xTF32 GEMM tile (64x64), split accumulators ----------------
// mode 1: leaky->fp32   2: leaky->split pair   3: h0 epilogue
__device__ void dev_gemm(const float* __restrict__ Ah, const float* __restrict__ Al, int K,
                         const float* __restrict__ Wh, const float* __restrict__ Wl, int MO,
                         float* __restrict__ O, float* __restrict__ Olo,
                         int mode, int m0, int n0,
                         const float* __restrict__ q1, const float* __restrict__ q2, int qtar,
                         float* sm) {
    float* Ash = sm;
    float* Asl = sm + 4352;
    float* Wsh = sm + 8704;
    float* Wsl = sm + 13056;
    float* Cs  = sm + 8704;   // reused after k-loop
    int tid = threadIdx.x;
    int warp = tid >> 5, wr = warp >> 1, wc = warp & 1;
    FragC accP[2], accE[2];
    #pragma unroll
    for (int t = 0; t < 2; t++) { wmma::fill_fragment(accP[t], 0.f); wmma::fill_fragment(accE[t], 0.f); }

    for (int k0 = 0; k0 < K; k0 += BKB) {
        stage64(Ah, Al, m0, k0, K, Ash, Asl);
        stage64(Wh, Wl, k0, n0, MO, Wsh, Wsl);
        __syncthreads();
        #pragma unroll
        for (int kk = 0; kk < BKB; kk += 8) {
            FragA ah, al;
            wmma::load_matrix_sync(ah, &Ash[(wr * 16) * 68 + kk], 68);
            wmma::load_matrix_sync(al, &Asl[(wr * 16) * 68 + kk], 68);
            #pragma unroll
            for (int t = 0; t < 2; t++) {
                FragB bh, bl;
                wmma::load_matrix_sync(bh, &Wsh[kk * 68 + wc * 32 + t * 16], 68);
                wmma::load_matrix_sync(bl, &Wsl[kk * 68 + wc * 32 + t * 16], 68);
                wmma::mma_sync(accP[t], ah, bh, accP[t]);
                wmma::mma_sync(accE[t], al, bh, accE[t]);
                wmma::mma_sync(accE[t], ah, bl, accE[t]);
            }
        }
        __syncthreads();
    }

    if (mode == 1) {
        #pragma unroll
        for (int t = 0; t < 2; t++) {
            #pragma unroll
            for (int e = 0; e < accP[t].num_elements; e++)
                accP[t].x[e] = lrelu(accP[t].x[e] + accE[t].x[e]);
            wmma::store_matrix_sync(O + (size_t)(m0 + wr * 16) * MO + n0 + wc * 32 + t * 16,
                                    accP[t], MO, wmma::mem_row_major);
        }
        return;
    }
    if (mode == 2) {
        #pragma unroll
        for (int t = 0; t < 2; t++) {
            FragC flo;
            #pragma unroll
            for (int e = 0; e < accP[t].num_elements; e++) {
                float v = lrelu(accP[t].x[e] + accE[t].x[e]);
                fsplit(v, accP[t].x[e], flo.x[e]);
            }
            size_t off = (size_t)(m0 + wr * 16) * MO + n0 + wc * 32 + t * 16;
            wmma::store_matrix_sync(O + off, accP[t], MO, wmma::mem_row_major);
            wmma::store_matrix_sync(Olo + off, flo, MO, wmma::mem_row_major);
        }
        return;
    }

    // mode 3: h0 = [a | q | a*q] split planes, element-addressed via smem
    #pragma unroll
    for (int t = 0; t < 2; t++) {
        #pragma unroll
        for (int e = 0; e < accP[t].num_elements; e++) accP[t].x[e] += accE[t].x[e];
        wmma::store_matrix_sync(&Cs[(wr * 16) * 68 + wc * 32 + t * 16], accP[t], 68,
                                wmma::mem_row_major);
    }
    __syncthreads();
    int r = tid >> 2, cbase = (tid & 3) * 16;
    int node = m0 + r;
    size_t hb = (size_t)node * 384;
    size_t qoff = qtar ? (size_t)(node >> 6) * 128 : (size_t)node * 128;
    #pragma unroll 4
    for (int j = 0; j < 16; j++) {
        int kg = n0 + cbase + j;
        float av = Cs[r * 68 + cbase + j];
        float qh = q1[qoff + kg], ql = q2[qoff + kg];
        float qv = qh + ql;
        float hh, hl;
        fsplit(av, hh, hl);
        O[hb + kg] = hh;            Olo[hb + kg] = hl;
        O[hb + 128 + kg] = qh;      Olo[hb + 128 + kg] = ql;
        fsplit(av * qv, hh, hl);
        O[hb + 256 + kg] = hh;      Olo[hb + 256 + kg] = hl;
    }
    __syncthreads();
}

// ---------------- fused h2 GEMM (64x128, K=256) + W3 dot + batch softmax -----------
__device__ void dev_h2fsm(const float* __restrict__ H1h, const float* __restrict__ H1l,
                          const float* __restrict__ W2h, const float* __restrict__ W2l,
                          const float* __restrict__ W3h, float* __restrict__ fout,
                          int b, float* sm) {
    float* Ash = sm;
    float* Asl = sm + 4352;
    float* Wsh = sm + 8704;
    float* Wsl = sm + 13056;
    float* Cs  = sm + 17408;   // [64][132]
    int tid = threadIdx.x;
    int warp = tid >> 5, wr = warp >> 1, wc = warp & 1;

    for (int nh = 0; nh < 2; nh++) {
        int n0 = nh * 64;
        FragC accP[2], accE[2];
        #pragma unroll
        for (int t = 0; t < 2; t++) { wmma::fill_fragment(accP[t], 0.f); wmma::fill_fragment(accE[t], 0.f); }
        for (int k0 = 0; k0 < 256; k0 += BKB) {
            stage64(H1h, H1l, b * 64, k0, 256, Ash, Asl);
            stage64(W2h, W2l, k0, n0, 128, Wsh, Wsl);
            __syncthreads();
            #pragma unroll
            for (int kk = 0; kk < BKB; kk += 8) {
                FragA ah, al;
                wmma::load_matrix_sync(ah, &Ash[(wr * 16) * 68 + kk], 68);
                wmma::load_matrix_sync(al, &Asl[(wr * 16) * 68 + kk], 68);
                #pragma unroll
                for (int t = 0; t < 2; t++) {
                    FragB bh, bl;
                    wmma::load_matrix_sync(bh, &Wsh[kk * 68 + wc * 32 + t * 16], 68);
                    wmma::load_matrix_sync(bl, &Wsl[kk * 68 + wc * 32 + t * 16], 68);
                    wmma::mma_sync(accP[t], ah, bh, accP[t]);
                    wmma::mma_sync(accE[t], al, bh, accE[t]);
                    wmma::mma_sync(accE[t], ah, bl, accE[t]);
                }
            }
            __syncthreads();
        }
        #pragma unroll
        for (int t = 0; t < 2; t++) {
            #pragma unroll
            for (int e = 0; e < accP[t].num_elements; e++)
                accP[t].x[e] = lrelu(accP[t].x[e] + accE[t].x[e]);
            wmma::store_matrix_sync(&Cs[(wr * 16) * 132 + n0 + wc * 32 + t * 16], accP[t], 132,
                                    wmma::mem_row_major);
        }
        __syncthreads();
    }

    // W3 dot + leaky + softmax over the 64 rows
    float* w3s = Ash;
    float* red = Asl;
    if (tid < 128) w3s[tid] = W3h[tid];
    __syncthreads();
    float v = 0.f;
    if (tid < 64) {
        float dot = 0.f;
        #pragma unroll 8
        for (int k = 0; k < 128; k++) dot += Cs[tid * 132 + k] * w3s[k];
        v = lrelu(dot);
        red[tid] = v;
    }
    __syncthreads();
    for (int off = 32; off > 0; off >>= 1) {
        if (tid < off) red[tid] = fmaxf(red[tid], red[tid + off]);
        __syncthreads();
    }
    float m = red[0];
    __syncthreads();
    float e = 0.f;
    if (tid < 64) { e = expf(v - m); red[tid] = e; }
    __syncthreads();
    for (int off = 32; off > 0; off >>= 1) {
        if (tid < off) red[tid] += red[tid + off];
        __syncthreads();
    }
    if (tid < 64) fout[b * 64 + tid] = e / red[0];
    __syncthreads();
}

// ---------------- x_c dual-weight GEMM (weights from global) ----------------
__device__ void dev_gemm_xc(const float* __restrict__ Ah, const float* __restrict__ Al,
                            const float* __restrict__ Wh, const float* __restrict__ Wl,
                            const float* __restrict__ W2h, const float* __restrict__ W2l,
                            const float* __restrict__ xorig,
                            float* __restrict__ O, float* __restrict__ Olo,
                            int m0, int n0, float* sm) {
    float* Ash = sm;
    float* Asl = sm + 4352;
    float* Cs  = sm + 8704;
    int tid = threadIdx.x;
    int warp = tid >> 5, wr = warp >> 1, wc = warp & 1;
    FragC acc[2], acc2[2];
    #pragma unroll
    for (int t = 0; t < 2; t++) { wmma::fill_fragment(acc[t], 0.f); wmma::fill_fragment(acc2[t], 0.f); }
    for (int k0 = 0; k0 < 128; k0 += BKB) {
        stage64(Ah, Al, m0, k0, 128, Ash, Asl);
        __syncthreads();
        #pragma unroll
        for (int kk = 0; kk < BKB; kk += 8) {
            FragA ah, al;
            wmma::load_matrix_sync(ah, &Ash[(wr * 16) * 68 + kk], 68);
            wmma::load_matrix_sync(al, &Asl[(wr * 16) * 68 + kk], 68);
            #pragma unroll
            for (int t = 0; t < 2; t++) {
                FragB bh, bl;
                wmma::load_matrix_sync(bh, Wh + (size_t)(k0 + kk) * 128 + n0 + wc * 32 + t * 16, 128);
                wmma::load_matrix_sync(bl, Wl + (size_t)(k0 + kk) * 128 + n0 + wc * 32 + t * 16, 128);
                mma3(acc[t], ah, al, bh, bl);
                FragB ch, cl;
                wmma::load_matrix_sync(ch, W2h + (size_t)(k0 + kk) * 128 + n0 + wc * 32 + t * 16, 128);
                wmma::load_matrix_sync(cl, W2l + (size_t)(k0 + kk) * 128 + n0 + wc * 32 + t * 16, 128);
                mma3(acc2[t], ah, al, ch, cl);
            }
        }
        __syncthreads();
    }
    #pragma unroll
    for (int t = 0; t < 2; t++)
        wmma::store_matrix_sync(&Cs[(wr * 16) * 68 + wc * 32 + t * 16], acc[t], 68,
                                wmma::mem_row_major);
    __syncthreads();
    int r = tid >> 2, cbase = (tid & 3) * 16;
    int node = m0 + r;
    float t0v[16];
    #pragma unroll
    for (int j = 0; j < 16; j++) t0v[j] = Cs[r * 68 + cbase + j];
    __syncthreads();
    #pragma unroll
    for (int t = 0; t < 2; t++)
        wmma::store_matrix_sync(&Cs[(wr * 16) * 68 + wc * 32 + t * 16], acc2[t], 68,
                                wmma::mem_row_major);
    __syncthreads();
    const float* xrow = xorig + (size_t)node * 128;
    #pragma unroll 4
    for (int j = 0; j < 16; j++) {
        int kg = n0 + cbase + j;
        float xv = xrow[kg];
        float v = 0.5f * (lrelu(xv + t0v[j]) + lrelu(xv + Cs[r * 68 + cbase + j]));
        float hh, hl;
        fsplit(v, hh, hl);
        O[(size_t)node * 128 + kg] = hh;
        Olo[(size_t)node * 128 + kg] = hl;
    }
    __syncthreads();
}

// ---------------- M2 = Aw^T @ Aw^T per batch (64x64), split output ----------------
__device__ void dev_m2(const float* __restrict__ Aw, float* __restrict__ Ph,
                       float* __restrict__ Pl, float* sm) {
    float* Th = sm;
    float* Tl = sm + 4352;
    int tid = threadIdx.x;
    for (int i = tid; i < 4096; i += NTHR) {
        float hh, hl;
        fsplit(Aw[i], hh, hl);
        int r = i >> 6, c = i & 63;
        Th[c * 68 + r] = hh; Tl[c * 68 + r] = hl;
    }
    __syncthreads();
    int warp = tid >> 5, wr = warp >> 1, wc = warp & 1;
    FragC acc[2];
    #pragma unroll
    for (int t = 0; t < 2; t++) wmma::fill_fragment(acc[t], 0.f);
    for (int k0 = 0; k0 < 64; k0 += 8) {
        FragA ah, al;
        wmma::load_matrix_sync(ah, &Th[(wr * 16) * 68 + k0], 68);
        wmma::load_matrix_sync(al, &Tl[(wr * 16) * 68 + k0], 68);
        #pragma unroll
        for (int t = 0; t < 2; t++) {
            FragB bh, bl;
            wmma::load_matrix_sync(bh, &Th[k0 * 68 + wc * 32 + t * 16], 68);
            wmma::load_matrix_sync(bl, &Tl[k0 * 68 + wc * 32 + t * 16], 68);
            mma3(acc[t], ah, al, bh, bl);
        }
    }
    #pragma unroll
    for (int t = 0; t < 2; t++) {
        FragC flo;
        #pragma unroll
        for (int e = 0; e < acc[t].num_elements; e++)
            fsplit(acc[t].x[e], acc[t].x[e], flo.x[e]);
        size_t off = (size_t)(wr * 16) * 64 + wc * 32 + t * 16;
        wmma::store_matrix_sync(Ph + off, acc[t], 64, wmma::mem_row_major);
        wmma::store_matrix_sync(Pl + off, flo, 64, wmma::mem_row_major);
    }
    __syncthreads();
}

// ---------------- apply: out = M2 @ v, 64x64 half-tile ----------------
__device__ void dev_bapply(const float* __restrict__ Ph, const float* __restrict__ Pl,
                           const float* __restrict__ vh, const float* __restrict__ vl,
                           int n0, float* __restrict__ oh, float* __restrict__ ol,
                           float* sm) {
    float* Psh = sm;
    float* Psl = sm + 4352;
    int tid = threadIdx.x;
    for (int i = tid; i < 4096; i += NTHR) {
        int r = i >> 6, c = i & 63;
        Psh[r * 68 + c] = Ph[i];
        Psl[r * 68 + c] = Pl[i];
    }
    __syncthreads();
    int warp = tid >> 5, wr = warp >> 1, wc = warp & 1;
    FragC acc[2];
    #pragma unroll
    for (int t = 0; t < 2; t++) wmma::fill_fragment(acc[t], 0.f);
    for (int k0 = 0; k0 < 64; k0 += 8) {
        FragA ah, al;
        wmma::load_matrix_sync(ah, &Psh[(wr * 16) * 68 + k0], 68);
        wmma::load_matrix_sync(al, &Psl[(wr * 16) * 68 + k0], 68);
        #pragma unroll
        for (int t = 0; t < 2; t++) {
            FragB bh, bl;
            wmma::load_matrix_sync(bh, vh + (size_t)k0 * 128 + n0 + wc * 32 + t * 16, 128);
            wmma::load_matrix_sync(bl, vl + (size_t)k0 * 128 + n0 + wc * 32 + t * 16, 128);
            mma3(acc[t], ah, al, bh, bl);
        }
    }
    #pragma unroll
    for (int t = 0; t < 2; t++) {
        FragC flo;
        #pragma unroll
        for (int e = 0; e < acc[t].num_elements; e++)
            fsplit(acc[t].x[e], acc[t].x[e], flo.x[e]);
        size_t off = (size_t)(wr * 16) * 128 + n0 + wc * 32 + t * 16;
        wmma::store_matrix_sync(oh + off, acc[t], 128, wmma::mem_row_major);
        wmma::store_matrix_sync(ol + off, flo, 128, wmma::mem_row_major);
    }
    __syncthreads();
}

// ---------------- agg: out = S^T @ v (S fp32, split inline) ----------------
__device__ void dev_bgemmT(const float* __restrict__ Mb,
                           const float* __restrict__ vh, const float* __restrict__ vl,
                           float* __restrict__ oh, float* __restrict__ ol, float* sm) {
    float* MsTh = sm;
    float* MsTl = sm + 4352;
    int tid = threadIdx.x;
    for (int i = tid; i < 4096; i += NTHR) {
        float hh, hl;
        fsplit(Mb[i], hh, hl);
        MsTh[(i & 63) * 68 + (i >> 6)] = hh;
        MsTl[(i & 63) * 68 + (i >> 6)] = hl;
    }
    __syncthreads();
    int warp = tid >> 5, wr = warp >> 2, wc = warp & 3;
    FragC acc[2][2];
    #pragma unroll
    for (int i = 0; i < 2; i++)
        #pragma unroll
        for (int j = 0; j < 2; j++) wmma::fill_fragment(acc[i][j], 0.f);
    for (int k0 = 0; k0 < 64; k0 += 8) {
        FragA ah[2], al[2];
        #pragma unroll
        for (int i = 0; i < 2; i++) {
            wmma::load_matrix_sync(ah[i], &MsTh[(wr * 32 + i * 16) * 68 + k0], 68);
            wmma::load_matrix_sync(al[i], &MsTl[(wr * 32 + i * 16) * 68 + k0], 68);
        }
        #pragma unroll
        for (int j = 0; j < 2; j++) {
            FragB bh, bl;
            wmma::load_matrix_sync(bh, vh + (size_t)k0 * 128 + wc * 32 + j * 16, 128);
            wmma::load_matrix_sync(bl, vl + (size_t)k0 * 128 + wc * 32 + j * 16, 128);
            #pragma unroll
            for (int i = 0; i < 2; i++) mma3(acc[i][j], ah[i], al[i], bh, bl);
        }
    }
    #pragma unroll
    for (int i = 0; i < 2; i++)
        #pragma unroll
        for (int j = 0; j < 2; j++) {
            FragC flo;
            #pragma unroll
            for (int e = 0; e < acc[i][j].num_elements; e++)
                fsplit(acc[i][j].x[e], acc[i][j].x[e], flo.x[e]);
            size_t off = (size_t)(wr * 32 + i * 16) * 128 + wc * 32 + j * 16;
            wmma::store_matrix_sync(oh + off, acc[i][j], 128, wmma::mem_row_major);
            wmma::store_matrix_sync(ol + off, flo, 128, wmma::mem_row_major);
        }
    __syncthreads();
}

// ---------------- attention pair (2 heads): h0 / h1 / fused h2+fsm ----------------
__device__ void attn_pair(const float* __restrict__ kvh, const float* __restrict__ kvl,
                          const float* __restrict__ qh, const float* __restrict__ ql,
                          int khead, const float* __restrict__ W3,
                          float* sc, float* sm, int bar0) {
    int bid = blockIdx.x;
    for (int tix = bid; tix < 256; tix += NBLK) {       // a = kv@Wk, fused h0 build
        int head = tix >> 7, rem = tix & 127;
        int m0 = (rem & 63) * 64, n0 = (rem >> 6) * 64;
        const float* wkh = sc + WKP + (size_t)(khead + head) * 16384;
        float* h0h = sc + H0P + (size_t)head * 3145728;
        dev_gemm(kvh, kvl, 128, wkh, wkh + 65536, 128,
                 h0h, h0h + 1572864, 3, m0, n0,
                 head ? sc + TGP : qh, head ? sc + TGP + 8192 : ql, head ? 1 : 0, sm);
    }
    gsync(bar0);
    for (int tix = bid; tix < 512; tix += NBLK) {       // h1 = leaky(h0 @ Wm), split out
        int head = tix >> 8, rem = tix & 255;
        int m0 = (rem & 63) * 64, n0 = (rem >> 6) * 64;
        const float* h0h = sc + H0P + (size_t)head * 3145728;
        const float* wmh = sc + WMP + (size_t)(khead + head) * 98304;
        float* h1h = sc + H1P + (size_t)head * 2097152;
        dev_gemm(h0h, h0h + 1572864, 384, wmh, wmh + 393216, 256,
                 h1h, h1h + 1048576, 2, m0, n0, nullptr, nullptr, 0, sm);
    }
    gsync(bar0 + 1);
    if (bid < 128) {                                    // fused h2 + W3 dot + softmax
        int head = bid >> 6, b = bid & 63;
        const float* h1h = sc + H1P + (size_t)head * 2097152;
        const float* w2h = sc + W2P + (size_t)(khead + head) * 32768;
        dev_h2fsm(h1h, h1h + 1048576, w2h, w2h + 131072,
                  W3 + (size_t)(khead + head) * 128,
                  sc + FO + (size_t)head * 4096, b, sm);
    }
    gsync(bar0 + 2);
}

// ==================== megakernel ====================
__global__ void __launch_bounds__(NTHR, 2)
mega(const float* __restrict__ x, const int* __restrict__ ei,
     const float* __restrict__ ew, const float* __restrict__ tgt,
     const float* __restrict__ Wk, const float* __restrict__ W1,
     const float* __restrict__ W2, const float* __restrict__ W3,
     const float* __restrict__ lW, float* __restrict__ out) {
    extern __shared__ __align__(16) float sm[];
    float* sc = g_scratch;
    int bid = blockIdx.x, tid = threadIdx.x;
    int gth = bid * NTHR + tid;
    const int GSTR = NBLK * NTHR;

    // ---- B0: split planes; zero Aw/cnt/deg + A2 ----
    for (int i = gth; i < 4 * 384 * 256; i += GSTR) {   // Wm = [Wa+Wc; Wb-Wc; Wd]
        int c = i & 255, r = (i >> 8) % 384, h = i / (384 * 256);
        const float* Wh = W1 + (size_t)h * 512 * 256;
        float v;
        if (r < 128)      v = Wh[r * 256 + c] + Wh[(256 + r) * 256 + c];
        else if (r < 256) v = Wh[r * 256 + c] - Wh[(r + 128) * 256 + c];
        else              v = Wh[(r + 128) * 256 + c];
        fsplit(v, sc[WMP + i], sc[WMP + 393216 + i]);
    }
    for (int i = gth; i < 4 * 16384; i += GSTR)  fsplit(Wk[i], sc[WKP + i], sc[WKP + 65536 + i]);
    for (int i = gth; i < 4 * 32768; i += GSTR)  fsplit(W2[i], sc[W2P + i], sc[W2P + 131072 + i]);
    for (int i = gth; i < 2 * 16384; i += GSTR)  fsplit(lW[i], sc[LWP + i], sc[LWP + 32768 + i]);
    for (int i = gth; i < NTOT * 128; i += GSTR) fsplit(x[i],  sc[XP + i],  sc[XP + 524288 + i]);
    for (int i = gth; i < NBAT * 128; i += GSTR) fsplit(tgt[i], sc[TGP + i], sc[TGP + 8192 + i]);
    {
        float4 z = make_float4(0.f, 0.f, 0.f, 0.f);
        float4* p = (float4*)(sc + AWO);
        for (int i = gth; i < 528384 / 4; i += GSTR) p[i] = z;
        float4* p2 = (float4*)(out + O_A2);
        for (int i = gth; i < (NKEEP * NKEEP) / 4; i += GSTR) p2[i] = z;
    }
    gsync(0);

    // ---- B1: degree ----
    for (int e = gth; e < NEDG + NTOT; e += GSTR) {
        if (e < NEDG) atomicAdd(&sc[DEGO + ei[NEDG + e]], ew[e]);
        else          atomicAdd(&sc[DEGO + e - NEDG], 1.0f);
    }
    gsync(1);

    // ---- B2: dense adjacency with inline dinv ----
    for (int e = gth; e < NEDG + NTOT; e += GSTR) {
        int r, c; float wv;
        if (e < NEDG) { r = ei[e]; c = ei[NEDG + e]; wv = ew[e]; }
        else          { r = c = e - NEDG; wv = 1.f; }
        float dr = sc[DEGO + r], dc = sc[DEGO + c];
        float ir = dr > 0.f ? rsqrtf(fmaxf(dr, 1e-12f)) : 0.f;
        float ic = dc > 0.f ? rsqrtf(fmaxf(dc, 1e-12f)) : 0.f;
        int o = ((r >> 6) << 12) + ((r & 63) << 6) + (c & 63);
        atomicAdd(&sc[AWO + o], ir * wv * ic);
        atomicAdd(&sc[CNTO + o], 1.f);
    }
    gsync(2);

    // ---- B3: M2 = Aw^T Aw^T per batch ----
    if (bid < NBAT)
        dev_m2(sc + AWO + (size_t)bid * 4096,
               sc + M2P + (size_t)bid * 4096, sc + M2P + 262144 + (size_t)bid * 4096, sm);
    gsync(3);

    // ---- B4: x_q = M2 @ x ----
    if (bid < 2 * NBAT) {
        int b = bid >> 1, n0 = (bid & 1) * 64;
        dev_bapply(sc + M2P + (size_t)b * 4096, sc + M2P + 262144 + (size_t)b * 4096,
                   sc + XP + (size_t)b * 8192, sc + XP + 524288 + (size_t)b * 8192, n0,
                   sc + XQP + (size_t)b * 8192, sc + XQP + 524288 + (size_t)b * 8192, sm);
    }
    gsync(4);

    // ---- B5-B7: f1 = att(x, x_q), f2 = att(x, qt), fused fsm ----
    attn_pair(sc + XP, sc + XP + 524288, sc + XQP, sc + XQP + 524288, 0, W3, sc, sm, 5);

    // ---- B8: edge-softmax S, agg = S^T x ----
    if (bid < NBAT) {
        float* f1s = sm;
        float* f2s = sm + 64;
        if (tid < 64) {
            f1s[tid] = sc[FO + bid * 64 + tid];
            f2s[tid] = sc[FO + 4096 + bid * 64 + tid];
        }
        __syncthreads();
        if (tid < 64) {
            int c = tid;
            float f1c = f1s[c];
            const float* Cb = sc + CNTO + (size_t)bid * 4096;
            float* Sb = sc + SO + (size_t)bid * 4096;
            float m = -1e30f;
            for (int r = 0; r < 64; r++) m = fmaxf(m, lrelu(f1c + f2s[r]));
            float d = 0.f;
            for (int r = 0; r < 64; r++) {
                float val = lrelu(f1c + f2s[r]);
                float e = Cb[r * 64 + c] * expf(val - m);
                Sb[r * 64 + c] = e; d += e;
            }
            float inv = 1.f / d;
            for (int r = 0; r < 64; r++) Sb[r * 64 + c] *= inv;
        }
        __syncthreads();
        dev_bgemmT(sc + SO + (size_t)bid * 4096,
                   sc + XP + (size_t)bid * 8192, sc + XP + 524288 + (size_t)bid * 8192,
                   sc + AGP + (size_t)bid * 8192, sc + AGP + 524288 + (size_t)bid * 8192,
                   sm + 256);
    }
    gsync(8);

    // ---- B9: x_c = 0.5*(lrelu(x+agg@W0)+lrelu(x+agg@W1)) ----
    for (int tix = bid; tix < 128; tix += NBLK) {
        int m0 = (tix & 63) * 64, n0 = (tix >> 6) * 64;
        dev_gemm_xc(sc + AGP, sc + AGP + 524288,
                    sc + LWP, sc + LWP + 32768,
                    sc + LWP + 16384, sc + LWP + 49152, x,
                    sc + XCP, sc + XCP + 524288, m0, n0, sm);
    }
    gsync(9);

    // ---- B10: x_q2 = M2 @ x_c ----
    if (bid < 2 * NBAT) {
        int b = bid >> 1, n0 = (bid & 1) * 64;
        dev_bapply(sc + M2P + (size_t)b * 4096, sc + M2P + 262144 + (size_t)b * 4096,
                   sc + XCP + (size_t)b * 8192, sc + XCP + 524288 + (size_t)b * 8192, n0,
                   sc + XQP + (size_t)b * 8192, sc + XQP + 524288 + (size_t)b * 8192, sm);
    }
    gsync(10);

    // ---- B11-B13: g1 = att(x_c, x_q2), g2 = att(x_c, qt), fused fsm ----
    attn_pair(sc + XCP, sc + XCP + 524288, sc + XQP, sc + XQP + 524288, 2, W3, sc, sm, 11);

    // ---- B14: score softmax + rank top-k ----
    if (bid < NBAT) {
        float* red = sm;
        float* ss = sm + 64;
        float v = 0.f;
        if (tid < 64)
            v = sc[FO + bid * 64 + tid] + sc[FO + 4096 + bid * 64 + tid];
        if (tid < 64) red[tid] = v;
        __syncthreads();
        for (int off = 32; off > 0; off >>= 1) {
            if (tid < off) red[tid] = fmaxf(red[tid], red[tid + off]);
            __syncthreads();
        }
        float m = red[0];
        __syncthreads();
        float e = 0.f;
        if (tid < 64) { e = expf(v - m); red[tid] = e; }
        __syncthreads();
        for (int off = 32; off > 0; off >>= 1) {
            if (tid < off) red[tid] += red[tid + off];
            __syncthreads();
        }
        float si = (tid < 64) ? e / red[0] : 0.f;
        __syncthreads();
        if (tid < 64) ss[tid] = si;
        __syncthreads();
        if (tid < 64) {
            int rank = 0;
            for (int j = 0; j < 64; j++) {
                float sj = ss[j];
                rank += (sj > si) || (sj == si && j < tid);
            }
            sc[SCOREO + bid * 64 + tid] = si;
            if (rank < KSEL) ((int*)(sc + PERMO))[bid * KSEL + rank] = tid;
        }
    }
    gsync(14);

    // ---- B15: outputs ----
    if (bid < NBAT) {
        float* Aws = sm;           // [64][65]
        float* Sp  = sm + 4160;    // [64][53]
        float* Ms  = sm + 7552;    // [64][53]
        int*   idx = (int*)(sm + 10944);
        const int* perm = (const int*)(sc + PERMO);
        const float* Ab = sc + AWO + (size_t)bid * 4096;
        for (int i = tid; i < 4096; i += NTHR) Aws[(i >> 6) * 65 + (i & 63)] = Ab[i];
        if (tid < KSEL) idx[tid] = perm[bid * KSEL + tid];
        __syncthreads();
        const float* Sb = sc + SO + (size_t)bid * 4096;
        for (int i = tid; i < 64 * KSEL; i += NTHR) {
            int r = i / KSEL, j = i % KSEL;
            Sp[r * 53 + j] = Sb[r * 64 + idx[j]];
        }
        __syncthreads();
        for (int i = tid; i < 64 * KSEL; i += NTHR) {
            int r = i / KSEL, j = i % KSEL;
            float acc = 0.f;
            #pragma unroll 8
            for (int c = 0; c < 64; c++) acc += Aws[r * 65 + c] * Sp[c * 53 + j];
            Ms[r * 53 + j] = acc;
        }
        __syncthreads();
        for (int i = tid; i < KSEL * KSEL; i += NTHR) {
            int ii = i / KSEL, j = i % KSEL;
            float v;
            if (ii == j) v = 1.f;
            else {
                v = 0.f;
                #pragma unroll 8
                for (int r = 0; r < 64; r++) v += Sp[r * 53 + ii] * Ms[r * 53 + j];
            }
            long long gi = (long long)bid * KSEL + ii;
            out[O_A2 + gi * NKEEP + bid * KSEL + j] = v;
        }
    } else {
        const int* perm = (const int*)(sc + PERMO);
        for (int t = (bid - NBAT) * NTHR + tid; t < NKEEP * HDIM; t += (NBLK - NBAT) * NTHR) {
            int j = t >> 7, k = t & 127;
            int b = j / KSEL;
            int pg = b * 64 + perm[j];
            out[t] = x[(size_t)pg * 128 + k] * sc[SCOREO + pg];
            if (k == 0) {
                out[O_BAT + j]  = (float)b;
                out[O_PERM + j] = (float)pg;
            }
        }
    }
}

extern "C" void kernel_launch(void* const* d_in, const int* in_sizes, int n_in,
                              void* d_out, int out_size) {
    const float* x   = (const float*)d_in[0];
    const int*   ei  = (const int*)d_in[1];
    const float* ew  = (const float*)d_in[2];
    const float* tgt = (const float*)d_in[3];
    const float* Wk  = (const float*)d_in[5];
    const float* W1  = (const float*)d_in[6];
    const float* W2  = (const float*)d_in[7];
    const float* W3  = (const float*)d_in[8];
    const float* lW  = (const float*)d_in[9];
    cudaFuncSetAttribute(mega, cudaFuncAttributeMaxDynamicSharedMemorySize,
                         DSMEM_FLOATS * sizeof(float));
    mega<<<NBLK, NTHR, DSMEM_FLOATS * sizeof(float)>>>(x, ei, ew, tgt, Wk, W1, W2, W3, lW,
                                                       (float*)d_out);
}

// round 14
// speedup vs baseline: 1.1584x; 1.0122x over previous
#include <cuda_runtime.h>
#include <mma.h>
using namespace nvcuda;

// ---------------- problem constants ----------------
#define NTOT 4096
#define HDIM 128
#define NBAT 64
#define NEDG 131072
#define KSEL 52
#define NKEEP 3328
#define NBLK 296      // 2 CTAs/SM x 148 SMs, all co-resident
#define NTHR 256
#define DSMEM_FLOATS 25856     // 103424 bytes dynamic smem

// output layout (float32 flat): x_out, A2, batch_out, perm
#define O_A2   425984LL
#define O_BAT  11501568LL
#define O_PERM 11504896LL

// scratch offsets (floats); pair tensors: hi plane then lo plane
#define WMP    0LL         // combined W1: 4 x 384 x 256 pair (lo +393216)
#define WKP    786432LL    // Wk pair (lo +65536)
#define W2P    917504LL    // W2 pair (lo +131072)
#define LWP    1179648LL   // lin_W pair (lo +32768)
#define XP     1245184LL   // x pair (lo +524288)
#define TGP    2293760LL   // target pair (lo +8192)
#define XQP    2310144LL   // pair
#define AGP    3358720LL   // pair
#define XCP    4407296LL   // pair
#define M2P    5455872LL   // per-batch M2 pair (lo +262144)
#define H0P    5980160LL   // 2 heads x (4096x384 pair), head stride 3145728, lo +1572864
#define H1P    12271616LL  // 2 heads x (4096x256 pair), head stride 2097152, lo +1048576
#define FO     16465920LL  // per-stage f-values, 2 x 4096
#define AWO    16474112LL
#define CNTO   16736256LL
#define DEGO   16998400LL
#define SO     17002496LL
#define SCOREO 17264640LL
#define PERMO  17268736LL
#define SCRATCH_TOTAL 17272832LL

__device__ float g_scratch[SCRATCH_TOTAL];
__device__ unsigned g_bar[16 * 32];

__device__ __forceinline__ float lrelu(float v) { return v >= 0.f ? v : 0.01f * v; }

__device__ __forceinline__ void fsplit(float v, float& h, float& l) {
    h = wmma::__float_to_tf32(v);
    l = wmma::__float_to_tf32(v - h);
}

// monotonic-ticket grid barrier; gpu-scope fences flush L1D
__device__ __forceinline__ void gsync(int i) {
    __syncthreads();
    if (threadIdx.x == 0) {
        __threadfence();
        unsigned t = atomicAdd(&g_bar[i * 32], 1u);
        unsigned target = (t / NBLK + 1u) * NBLK;
        while ((int)(*(volatile unsigned*)&g_bar[i * 32] - target) < 0) { __nanosleep(64); }
        __threadfence();
    }
    __syncthreads();
}

typedef wmma::fragment<wmma::matrix_a, 16, 16, 8, wmma::precision::tf32, wmma::row_major> FragA;
typedef wmma::fragment<wmma::matrix_b, 16, 16, 8, wmma::precision::tf32, wmma::row_major> FragB;
typedef wmma::fragment<wmma::accumulator, 16, 16, 8, float> FragC;

__device__ __forceinline__ void mma3(FragC& d, const FragA& ah, const FragA& al,
                                     const FragB& bh, const FragB& bl) {
    wmma::mma_sync(d, al, bh, d);
    wmma::mma_sync(d, ah, bl, d);
    wmma::mma_sync(d, ah, bh, d);
}

// smem layout inside each GEMM helper (floats):
//   Ash 0, Asl 4352, Wsh 8704, Wsl 13056 (each [64][68]); Cs reuses 8704; H2 Cs at 17408
#define BKB 64

// stage a 64x64 chunk (both planes) of a row-major matrix into [64][68] smem tiles
__device__ __forceinline__ void stage64(const float* __restrict__ Ph,
                                        const float* __restrict__ Pl,
                                        int row0, int col0, int ld,
                                        float* __restrict__ Sh, float* __restrict__ Sl) {
    int tid = threadIdx.x;
    #pragma unroll
    for (int s = 0; s < 4; s++) {
        int i = tid + s * 256;
        int r = i >> 4, c = (i & 15) * 4;
        *(float4*)&Sh[r * 68 + c] = *(const float4*)(Ph + (size_t)(row0 + r) * ld + col0 + c);
        *(float4*)&Sl[r * 68 + c] = *(const float4*)(Pl + (size_t)(row0 + r) * ld + col0 + c);
    }
}

// ---------------- 3xTF32 GEMM tile (64x64), split accumulators ----------------
// mode 1: leaky->fp32   2: leaky->split pair   3: h0 epilogue
__device__ void dev_gemm(const float* __restrict__ Ah, const float* __restrict__ Al, int K,
                         const float* __restrict__ Wh, const float* __restrict__ Wl, int MO,
                         float* __restrict__ O, float* __restrict__ Olo,
                         int mode, int m0, int n0,
                         const float* __restrict__ q1, const float* __restrict__ q2, int qtar,
                         float* sm) {
    float* Ash = sm;
    float* Asl = sm + 4352;
    float* Wsh = sm + 8704;
    float* Wsl = sm + 13056;
    float* Cs  = sm + 8704;   // reused after k-loop
    int tid = threadIdx.x;
    int warp = tid >> 5, wr = warp >> 1, wc = warp & 1;
    FragC accP[2], accE[2];
    #pragma unroll
    for (int t = 0; t < 2; t++) { wmma::fill_fragment(accP[t], 0.f); wmma::fill_fragment(accE[t], 0.f); }

    for (int k0 = 0; k0 < K; k0 += BKB) {
        stage64(Ah, Al, m0, k0, K, Ash, Asl);
        stage64(Wh, Wl, k0, n0, MO, Wsh, Wsl);
        __syncthreads();
        #pragma unroll
        for (int kk = 0; kk < BKB; kk += 8) {
            FragA ah, al;
            wmma::load_matrix_sync(ah, &Ash[(wr * 16) * 68 + kk], 68);
            wmma::load_matrix_sync(al, &Asl[(wr * 16) * 68 + kk], 68);
            #pragma unroll
            for (int t = 0; t < 2; t++) {
                FragB bh, bl;
                wmma::load_matrix_sync(bh, &Wsh[kk * 68 + wc * 32 + t * 16], 68);
                wmma::load_matrix_sync(bl, &Wsl[kk * 68 + wc * 32 + t * 16], 68);
                wmma::mma_sync(accP[t], ah, bh, accP[t]);
                wmma::mma_sync(accE[t], al, bh, accE[t]);
                wmma::mma_sync(accE[t], ah, bl, accE[t]);
            }
        }
        __syncthreads();
    }

    if (mode == 1) {
        #pragma unroll
        for (int t = 0; t < 2; t++) {
            #pragma unroll
            for (int e = 0; e < accP[t].num_elements; e++)
                accP[t].x[e] = lrelu(accP[t].x[e] + accE[t].x[e]);
            wmma::store_matrix_sync(O + (size_t)(m0 + wr * 16) * MO + n0 + wc * 32 + t * 16,
                                    accP[t], MO, wmma::mem_row_major);
        }
        return;
    }
    if (mode == 2) {
        #pragma unroll
        for (int t = 0; t < 2; t++) {
            FragC flo;
            #pragma unroll
            for (int e = 0; e < accP[t].num_elements; e++) {
                float v = lrelu(accP[t].x[e] + accE[t].x[e]);
                fsplit(v, accP[t].x[e], flo.x[e]);
            }
            size_t off = (size_t)(m0 + wr * 16) * MO + n0 + wc * 32 + t * 16;
            wmma::store_matrix_sync(O + off, accP[t], MO, wmma::mem_row_major);
            wmma::store_matrix_sync(Olo + off, flo, MO, wmma::mem_row_major);
        }
        return;
    }

    // mode 3: h0 = [a | q | a*q] split planes, element-addressed via smem
    #pragma unroll
    for (int t = 0; t < 2; t++) {
        #pragma unroll
        for (int e = 0; e < accP[t].num_elements; e++) accP[t].x[e] += accE[t].x[e];
        wmma::store_matrix_sync(&Cs[(wr * 16) * 68 + wc * 32 + t * 16], accP[t], 68,
                                wmma::mem_row_major);
    }
    __syncthreads();
    int r = tid >> 2, cbase = (tid & 3) * 16;
    int node = m0 + r;
    size_t hb = (size_t)node * 384;
    size_t qoff = qtar ? (size_t)(node >> 6) * 128 : (size_t)node * 128;
    #pragma unroll 4
    for (int j = 0; j < 16; j++) {
        int kg = n0 + cbase + j;
        float av = Cs[r * 68 + cbase + j];
        float qh = q1[qoff + kg], ql = q2[qoff + kg];
        float qv = qh + ql;
        float hh, hl;
        fsplit(av, hh, hl);
        O[hb + kg] = hh;            Olo[hb + kg] = hl;
        O[hb + 128 + kg] = qh;      Olo[hb + 128 + kg] = ql;
        fsplit(av * qv, hh, hl);
        O[hb + 256 + kg] = hh;      Olo[hb + 256 + kg] = hl;
    }
    __syncthreads();
}

// ---------------- fused h2 GEMM (64x128, K=256) + W3 dot + batch softmax -----------
__device__ void dev_h2fsm(const float* __restrict__ H1h, const float* __restrict__ H1l,
                          const float* __restrict__ W2h, const float* __restrict__ W2l,
                          const float* __restrict__ W3h, float* __restrict__ fout,
                          int b, float* sm) {
    float* Ash = sm;
    float* Asl = sm + 4352;
    float* Wsh = sm + 8704;
    float* Wsl = sm + 13056;
    float* Cs  = sm + 17408;   // [64][132]
    int tid = threadIdx.x;
    int warp = tid >> 5, wr = warp >> 1, wc = warp & 1;

    for (int nh = 0; nh < 2; nh++) {
        int n0 = nh * 64;
        FragC accP[2], accE[2];
        #pragma unroll
        for (int t = 0; t < 2; t++) { wmma::fill_fragment(accP[t], 0.f); wmma::fill_fragment(accE[t], 0.f); }
        for (int k0 = 0; k0 < 256; k0 += BKB) {
            stage64(H1h, H1l, b * 64, k0, 256, Ash, Asl);
            stage64(W2h, W2l, k0, n0, 128, Wsh, Wsl);
            __syncthreads();
            #pragma unroll
            for (int kk = 0; kk < BKB; kk += 8) {
                FragA ah, al;
                wmma::load_matrix_sync(ah, &Ash[(wr * 16) * 68 + kk], 68);
                wmma::load_matrix_sync(al, &Asl[(wr * 16) * 68 + kk], 68);
                #pragma unroll
                for (int t = 0; t < 2; t++) {
                    FragB bh, bl;
                    wmma::load_matrix_sync(bh, &Wsh[kk * 68 + wc * 32 + t * 16], 68);
                    wmma::load_matrix_sync(bl, &Wsl[kk * 68 + wc * 32 + t * 16], 68);
                    wmma::mma_sync(accP[t], ah, bh, accP[t]);
                    wmma::mma_sync(accE[t], al, bh, accE[t]);
                    wmma::mma_sync(accE[t], ah, bl, accE[t]);
                }
            }
            __syncthreads();
        }
        #pragma unroll
        for (int t = 0; t < 2; t++) {
            #pragma unroll
            for (int e = 0; e < accP[t].num_elements; e++)
                accP[t].x[e] = lrelu(accP[t].x[e] + accE[t].x[e]);
            wmma::store_matrix_sync(&Cs[(wr * 16) * 132 + n0 + wc * 32 + t * 16], accP[t], 132,
                                    wmma::mem_row_major);
        }
        __syncthreads();
    }

    // W3 dot + leaky + softmax over the 64 rows
    float* w3s = Ash;
    float* red = Asl;
    if (tid < 128) w3s[tid] = W3h[tid];
    __syncthreads();
    float v = 0.f;
    if (tid < 64) {
        float dot = 0.f;
        #pragma unroll 8
        for (int k = 0; k < 128; k++) dot += Cs[tid * 132 + k] * w3s[k];
        v = lrelu(dot);
        red[tid] = v;
    }
    __syncthreads();
    for (int off = 32; off > 0; off >>= 1) {
        if (tid < off) red[tid] = fmaxf(red[tid], red[tid + off]);
        __syncthreads();
    }
    float m = red[0];
    __syncthreads();
    float e = 0.f;
    if (tid < 64) { e = expf(v - m); red[tid] = e; }
    __syncthreads();
    for (int off = 32; off > 0; off >>= 1) {
        if (tid < off) red[tid] += red[tid + off];
        __syncthreads();
    }
    if (tid < 64) fout[b * 64 + tid] = e / red[0];
    __syncthreads();
}

// ---------------- x_c dual-weight GEMM (weights from global) ----------------
__device__ void dev_gemm_xc(const float* __restrict__ Ah, const float* __restrict__ Al,
                            const float* __restrict__ Wh, const float* __restrict__ Wl,
                            const float* __restrict__ W2h, const float* __restrict__ W2l,
                            const float* __restrict__ xorig,
                            float* __restrict__ O, float* __restrict__ Olo,
                            int m0, int n0, float* sm) {
    float* Ash = sm;
    float* Asl = sm + 4352;
    float* Cs  = sm + 8704;
    int tid = threadIdx.x;
    int warp = tid >> 5, wr = warp >> 1, wc = warp & 1;
    FragC acc[2], acc2[2];
    #pragma unroll
    for (int t = 0; t < 2; t++) { wmma::fill_fragment(acc[t], 0.f); wmma::fill_fragment(acc2[t], 0.f); }
    for (int k0 = 0; k0 < 128; k0 += BKB) {
        stage64(Ah, Al, m0, k0, 128, Ash, Asl);
        __syncthreads();
        #pragma unroll
        for (int kk = 0; kk < BKB; kk += 8) {
            FragA ah, al;
            wmma::load_matrix_sync(ah, &Ash[(wr * 16) * 68 + kk], 68);
            wmma::load_matrix_sync(al, &Asl[(wr * 16) * 68 + kk], 68);
            #pragma unroll
            for (int t = 0; t < 2; t++) {
                FragB bh, bl;
                wmma::load_matrix_sync(bh, Wh + (size_t)(k0 + kk) * 128 + n0 + wc * 32 + t * 16, 128);
                wmma::load_matrix_sync(bl, Wl + (size_t)(k0 + kk) * 128 + n0 + wc * 32 + t * 16, 128);
                mma3(acc[t], ah, al, bh, bl);
                FragB ch, cl;
                wmma::load_matrix_sync(ch, W2h + (size_t)(k0 + kk) * 128 + n0 + wc * 32 + t * 16, 128);
                wmma::load_matrix_sync(cl, W2l + (size_t)(k0 + kk) * 128 + n0 + wc * 32 + t * 16, 128);
                mma3(acc2[t], ah, al, ch, cl);
            }
        }
        __syncthreads();
    }
    #pragma unroll
    for (int t = 0; t < 2; t++)
        wmma::store_matrix_sync(&Cs[(wr * 16) * 68 + wc * 32 + t * 16], acc[t], 68,
                                wmma::mem_row_major);
    __syncthreads();
    int r = tid >> 2, cbase = (tid & 3) * 16;
    int node = m0 + r;
    float t0v[16];
    #pragma unroll
    for (int j = 0; j < 16; j++) t0v[j] = Cs[r * 68 + cbase + j];
    __syncthreads();
    #pragma unroll
    for (int t = 0; t < 2; t++)
        wmma::store_matrix_sync(&Cs[(wr * 16) * 68 + wc * 32 + t * 16], acc2[t], 68,
                                wmma::mem_row_major);
    __syncthreads();
    const float* xrow = xorig + (size_t)node * 128;
    #pragma unroll 4
    for (int j = 0; j < 16; j++) {
        int kg = n0 + cbase + j;
        float xv = xrow[kg];
        float v = 0.5f * (lrelu(xv + t0v[j]) + lrelu(xv + Cs[r * 68 + cbase + j]));
        float hh, hl;
        fsplit(v, hh, hl);
        O[(size_t)node * 128 + kg] = hh;
        Olo[(size_t)node * 128 + kg] = hl;
    }
    __syncthreads();
}

// ---------------- M2 = Aw^T @ Aw^T per batch (64x64), split output ----------------
__device__ void dev_m2(const float* __restrict__ Aw, float* __restrict__ Ph,
                       float* __restrict__ Pl, float* sm) {
    float* Th = sm;
    float* Tl = sm + 4352;
    int tid = threadIdx.x;
    for (int i = tid; i < 4096; i += NTHR) {
        float hh, hl;
        fsplit(Aw[i], hh, hl);
        int r = i >> 6, c = i & 63;
        Th[c * 68 + r] = hh; Tl[c * 68 + r] = hl;
    }
    __syncthreads();
    int warp = tid >> 5, wr = warp >> 1, wc = warp & 1;
    FragC acc[2];
    #pragma unroll
    for (int t = 0; t < 2; t++) wmma::fill_fragment(acc[t], 0.f);
    for (int k0 = 0; k0 < 64; k0 += 8) {
        FragA ah, al;
        wmma::load_matrix_sync(ah, &Th[(wr * 16) * 68 + k0], 68);
        wmma::load_matrix_sync(al, &Tl[(wr * 16) * 68 + k0], 68);
        #pragma unroll
        for (int t = 0; t < 2; t++) {
            FragB bh, bl;
            wmma::load_matrix_sync(bh, &Th[k0 * 68 + wc * 32 + t * 16], 68);
            wmma::load_matrix_sync(bl, &Tl[k0 * 68 + wc * 32 + t * 16], 68);
            mma3(acc[t], ah, al, bh, bl);
        }
    }
    #pragma unroll
    for (int t = 0; t < 2; t++) {
        FragC flo;
        #pragma unroll
        for (int e = 0; e < acc[t].num_elements; e++)
            fsplit(acc[t].x[e], acc[t].x[e], flo.x[e]);
        size_t off = (size_t)(wr * 16) * 64 + wc * 32 + t * 16;
        wmma::store_matrix_sync(Ph + off, acc[t], 64, wmma::mem_row_major);
        wmma::store_matrix_sync(Pl + off, flo, 64, wmma::mem_row_major);
    }
    __syncthreads();
}

// ---------------- apply: out = M2 @ v, 64x64 half-tile ----------------
__device__ void dev_bapply(const float* __restrict__ Ph, const float* __restrict__ Pl,
                           const float* __restrict__ vh, const float* __restrict__ vl,
                           int n0, float* __restrict__ oh, float* __restrict__ ol,
                           float* sm) {
    float* Psh = sm;
    float* Psl = sm + 4352;
    int tid = threadIdx.x;
    for (int i = tid; i < 4096; i += NTHR) {
        int r = i >> 6, c = i & 63;
        Psh[r * 68 + c] = Ph[i];
        Psl[r * 68 + c] = Pl[i];
    }
    __syncthreads();
    int warp = tid >> 5, wr = warp >> 1, wc = warp & 1;
    FragC acc[2];
    #pragma unroll
    for (int t = 0; t < 2; t++) wmma::fill_fragment(acc[t], 0.f);
    for (int k0 = 0; k0 < 64; k0 += 8) {
        FragA ah, al;
        wmma::load_matrix_sync(ah, &Psh[(wr * 16) * 68 + k0], 68);
        wmma::load_matrix_sync(al, &Psl[(wr * 16) * 68 + k0], 68);
        #pragma unroll
        for (int t = 0; t < 2; t++) {
            FragB bh, bl;
            wmma::load_matrix_sync(bh, vh + (size_t)k0 * 128 + n0 + wc * 32 + t * 16, 128);
            wmma::load_matrix_sync(bl, vl + (size_t)k0 * 128 + n0 + wc * 32 + t * 16, 128);
            mma3(acc[t], ah, al, bh, bl);
        }
    }
    #pragma unroll
    for (int t = 0; t < 2; t++) {
        FragC flo;
        #pragma unroll
        for (int e = 0; e < acc[t].num_elements; e++)
            fsplit(acc[t].x[e], acc[t].x[e], flo.x[e]);
        size_t off = (size_t)(wr * 16) * 128 + n0 + wc * 32 + t * 16;
        wmma::store_matrix_sync(oh + off, acc[t], 128, wmma::mem_row_major);
        wmma::store_matrix_sync(ol + off, flo, 128, wmma::mem_row_major);
    }
    __syncthreads();
}

// ---------------- agg: out = S^T @ v (S fp32, split inline) ----------------
__device__ void dev_bgemmT(const float* __restrict__ Mb,
                           const float* __restrict__ vh, const float* __restrict__ vl,
                           float* __restrict__ oh, float* __restrict__ ol, float* sm) {
    float* MsTh = sm;
    float* MsTl = sm + 4352;
    int tid = threadIdx.x;
    for (int i = tid; i < 4096; i += NTHR) {
        float hh, hl;
        fsplit(Mb[i], hh, hl);
        MsTh[(i & 63) * 68 + (i >> 6)] = hh;
        MsTl[(i & 63) * 68 + (i >> 6)] = hl;
    }
    __syncthreads();
    int warp = tid >> 5, wr = warp >> 2, wc = warp & 3;
    FragC acc[2][2];
    #pragma unroll
    for (int i = 0; i < 2; i++)
        #pragma unroll
        for (int j = 0; j < 2; j++) wmma::fill_fragment(acc[i][j], 0.f);
    for (int k0 = 0; k0 < 64; k0 += 8) {
        FragA ah[2], al[2];
        #pragma unroll
        for (int i = 0; i < 2; i++) {
            wmma::load_matrix_sync(ah[i], &MsTh[(wr * 32 + i * 16) * 68 + k0], 68);
            wmma::load_matrix_sync(al[i], &MsTl[(wr * 32 + i * 16) * 68 + k0], 68);
        }
        #pragma unroll
        for (int j = 0; j < 2; j++) {
            FragB bh, bl;
            wmma::load_matrix_sync(bh, vh + (size_t)k0 * 128 + wc * 32 + j * 16, 128);
            wmma::load_matrix_sync(bl, vl + (size_t)k0 * 128 + wc * 32 + j * 16, 128);
            #pragma unroll
            for (int i = 0; i < 2; i++) mma3(acc[i][j], ah[i], al[i], bh, bl);
        }
    }
    #pragma unroll
    for (int i = 0; i < 2; i++)
        #pragma unroll
        for (int j = 0; j < 2; j++) {
            FragC flo;
            #pragma unroll
            for (int e = 0; e < acc[i][j].num_elements; e++)
                fsplit(acc[i][j].x[e], acc[i][j].x[e], flo.x[e]);
            size_t off = (size_t)(wr * 32 + i * 16) * 128 + wc * 32 + j * 16;
            wmma::store_matrix_sync(oh + off, acc[i][j], 128, wmma::mem_row_major);
            wmma::store_matrix_sync(ol + off, flo, 128, wmma::mem_row_major);
        }
    __syncthreads();
}

// ---------------- attention pair (2 heads): h0 / h1 / fused h2+fsm ----------------
__device__ void attn_pair(const float* __restrict__ kvh, const float* __restrict__ kvl,
                          const float* __restrict__ qh, const float* __restrict__ ql,
                          int khead, const float* __restrict__ W3,
                          float* sc, float* sm, int bar0) {
    int bid = blockIdx.x;
    for (int tix = bid; tix < 256; tix += NBLK) {       // a = kv@Wk, fused h0 build
        int head = tix >> 7, rem = tix & 127;
        int m0 = (rem & 63) * 64, n0 = (rem >> 6) * 64;
        const float* wkh = sc + WKP + (size_t)(khead + head) * 16384;
        float* h0h = sc + H0P + (size_t)head * 3145728;
        dev_gemm(kvh, kvl, 128, wkh, wkh + 65536, 128,
                 h0h, h0h + 1572864, 3, m0, n0,
                 head ? sc + TGP : qh, head ? sc + TGP + 8192 : ql, head ? 1 : 0, sm);
    }
    gsync(bar0);
    for (int tix = bid; tix < 512; tix += NBLK) {       // h1 = leaky(h0 @ Wm), split out
        int head = tix >> 8, rem = tix & 255;
        int m0 = (rem & 63) * 64, n0 = (rem >> 6) * 64;
        const float* h0h = sc + H0P + (size_t)head * 3145728;
        const float* wmh = sc + WMP + (size_t)(khead + head) * 98304;
        float* h1h = sc + H1P + (size_t)head * 2097152;
        dev_gemm(h0h, h0h + 1572864, 384, wmh, wmh + 393216, 256,
                 h1h, h1h + 1048576, 2, m0, n0, nullptr, nullptr, 0, sm);
    }
    gsync(bar0 + 1);
    if (bid < 128) {                                    // fused h2 + W3 dot + softmax
        int head = bid >> 6, b = bid & 63;
        const float* h1h = sc + H1P + (size_t)head * 2097152;
        const float* w2h = sc + W2P + (size_t)(khead + head) * 32768;
        dev_h2fsm(h1h, h1h + 1048576, w2h, w2h + 131072,
                  W3 + (size_t)(khead + head) * 128,
                  sc + FO + (size_t)head * 4096, b, sm);
    }
    gsync(bar0 + 2);
}

// ==================== megakernel ====================
__global__ void __launch_bounds__(NTHR, 2)
mega(const float* __restrict__ x, const int* __restrict__ ei,
     const float* __restrict__ ew, const float* __restrict__ tgt,
     const float* __restrict__ Wk, const float* __restrict__ W1,
     const float* __restrict__ W2, const float* __restrict__ W3,
     const float* __restrict__ lW, float* __restrict__ out) {
    extern __shared__ __align__(16) float sm[];
    float* sc = g_scratch;
    int bid = blockIdx.x, tid = threadIdx.x;
    int gth = bid * NTHR + tid;
    const int GSTR = NBLK * NTHR;

    // ---- B0: split planes; zero Aw/cnt/deg + A2 ----
    for (int i = gth; i < 4 * 384 * 256; i += GSTR) {   // Wm = [Wa+Wc; Wb-Wc; Wd]
        int c = i & 255, r = (i >> 8) % 384, h = i / (384 * 256);
        const float* Wh = W1 + (size_t)h * 512 * 256;
        float v;
        if (r < 128)      v = Wh[r * 256 + c] + Wh[(256 + r) * 256 + c];
        else if (r < 256) v = Wh[r * 256 + c] - Wh[(r + 128) * 256 + c];
        else              v = Wh[(r + 128) * 256 + c];
        fsplit(v, sc[WMP + i], sc[WMP + 393216 + i]);
    }
    for (int i = gth; i < 4 * 16384; i += GSTR)  fsplit(Wk[i], sc[WKP + i], sc[WKP + 65536 + i]);
    for (int i = gth; i < 4 * 32768; i += GSTR)  fsplit(W2[i], sc[W2P + i], sc[W2P + 131072 + i]);
    for (int i = gth; i < 2 * 16384; i += GSTR)  fsplit(lW[i], sc[LWP + i], sc[LWP + 32768 + i]);
    for (int i = gth; i < NTOT * 128; i += GSTR) fsplit(x[i],  sc[XP + i],  sc[XP + 524288 + i]);
    for (int i = gth; i < NBAT * 128; i += GSTR) fsplit(tgt[i], sc[TGP + i], sc[TGP + 8192 + i]);
    {
        float4 z = make_float4(0.f, 0.f, 0.f, 0.f);
        float4* p = (float4*)(sc + AWO);
        for (int i = gth; i < 528384 / 4; i += GSTR) p[i] = z;
        float4* p2 = (float4*)(out + O_A2);
        for (int i = gth; i < (NKEEP * NKEEP) / 4; i += GSTR) p2[i] = z;
    }
    gsync(0);

    // ---- B1: degree ----
    for (int e = gth; e < NEDG + NTOT; e += GSTR) {
        if (e < NEDG) atomicAdd(&sc[DEGO + ei[NEDG + e]], ew[e]);
        else          atomicAdd(&sc[DEGO + e - NEDG], 1.0f);
    }
    gsync(1);

    // ---- B2: dense adjacency with inline dinv ----
    for (int e = gth; e < NEDG + NTOT; e += GSTR) {
        int r, c; float wv;
        if (e < NEDG) { r = ei[e]; c = ei[NEDG + e]; wv = ew[e]; }
        else          { r = c = e - NEDG; wv = 1.f; }
        float dr = sc[DEGO + r], dc = sc[DEGO + c];
        float ir = dr > 0.f ? rsqrtf(fmaxf(dr, 1e-12f)) : 0.f;
        float ic = dc > 0.f ? rsqrtf(fmaxf(dc, 1e-12f)) : 0.f;
        int o = ((r >> 6) << 12) + ((r & 63) << 6) + (c & 63);
        atomicAdd(&sc[AWO + o], ir * wv * ic);
        atomicAdd(&sc[CNTO + o], 1.f);
    }
    gsync(2);

    // ---- B3: M2 = Aw^T Aw^T per batch ----
    if (bid < NBAT)
        dev_m2(sc + AWO + (size_t)bid * 4096,
               sc + M2P + (size_t)bid * 4096, sc + M2P + 262144 + (size_t)bid * 4096, sm);
    gsync(3);

    // ---- B4: x_q = M2 @ x ----
    if (bid < 2 * NBAT) {
        int b = bid >> 1, n0 = (bid & 1) * 64;
        dev_bapply(sc + M2P + (size_t)b * 4096, sc + M2P + 262144 + (size_t)b * 4096,
                   sc + XP + (size_t)b * 8192, sc + XP + 524288 + (size_t)b * 8192, n0,
                   sc + XQP + (size_t)b * 8192, sc + XQP + 524288 + (size_t)b * 8192, sm);
    }
    gsync(4);

    // ---- B5-B7: f1 = att(x, x_q), f2 = att(x, qt), fused fsm ----
    attn_pair(sc + XP, sc + XP + 524288, sc + XQP, sc + XQP + 524288, 0, W3, sc, sm, 5);

    // ---- B8: edge-softmax S, agg = S^T x ----
    if (bid < NBAT) {
        float* f1s = sm;
        float* f2s = sm + 64;
        if (tid < 64) {
            f1s[tid] = sc[FO + bid * 64 + tid];
            f2s[tid] = sc[FO + 4096 + bid * 64 + tid];
        }
        __syncthreads();
        if (tid < 64) {
            int c = tid;
            float f1c = f1s[c];
            const float* Cb = sc + CNTO + (size_t)bid * 4096;
            float* Sb = sc + SO + (size_t)bid * 4096;
            float m = -1e30f;
            for (int r = 0; r < 64; r++) m = fmaxf(m, lrelu(f1c + f2s[r]));
            float d = 0.f;
            for (int r = 0; r < 64; r++) {
                float val = lrelu(f1c + f2s[r]);
                float e = Cb[r * 64 + c] * expf(val - m);
                Sb[r * 64 + c] = e; d += e;
            }
            float inv = 1.f / d;
            for (int r = 0; r < 64; r++) Sb[r * 64 + c] *= inv;
        }
        __syncthreads();
        dev_bgemmT(sc + SO + (size_t)bid * 4096,
                   sc + XP + (size_t)bid * 8192, sc + XP + 524288 + (size_t)bid * 8192,
                   sc + AGP + (size_t)bid * 8192, sc + AGP + 524288 + (size_t)bid * 8192,
                   sm + 256);
    }
    gsync(8);

    // ---- B9: x_c = 0.5*(lrelu(x+agg@W0)+lrelu(x+agg@W1)) ----
    for (int tix = bid; tix < 128; tix += NBLK) {
        int m0 = (tix & 63) * 64, n0 = (tix >> 6) * 64;
        dev_gemm_xc(sc + AGP, sc + AGP + 524288,
                    sc + LWP, sc + LWP + 32768,
                    sc + LWP + 16384, sc + LWP + 49152, x,
                    sc + XCP, sc + XCP + 524288, m0, n0, sm);
    }
    gsync(9);

    // ---- B10: x_q2 = M2 @ x_c ----
    if (bid < 2 * NBAT) {
        int b = bid >> 1, n0 = (bid & 1) * 64;
        dev_bapply(sc + M2P + (size_t)b * 4096, sc + M2P + 262144 + (size_t)b * 4096,
                   sc + XCP + (size_t)b * 8192, sc + XCP + 524288 + (size_t)b * 8192, n0,
                   sc + XQP + (size_t)b * 8192, sc + XQP + 524288 + (size_t)b * 8192, sm);
    }
    gsync(10);

    // ---- B11-B13: g1 = att(x_c, x_q2), g2 = att(x_c, qt), fused fsm ----
    attn_pair(sc + XCP, sc + XCP + 524288, sc + XQP, sc + XQP + 524288, 2, W3, sc, sm, 11);

    // ---- B14: score softmax + rank top-k ----
    if (bid < NBAT) {
        float* red = sm;
        float* ss = sm + 64;
        float v = 0.f;
        if (tid < 64)
            v = sc[FO + bid * 64 + tid] + sc[FO + 4096 + bid * 64 + tid];
        if (tid < 64) red[tid] = v;
        __syncthreads();
        for (int off = 32; off > 0; off >>= 1) {
            if (tid < off) red[tid] = fmaxf(red[tid], red[tid + off]);
            __syncthreads();
        }
        float m = red[0];
        __syncthreads();
        float e = 0.f;
        if (tid < 64) { e = expf(v - m); red[tid] = e; }
        __syncthreads();
        for (int off = 32; off > 0; off >>= 1) {
            if (tid < off) red[tid] += red[tid + off];
            __syncthreads();
        }
        float si = (tid < 64) ? e / red[0] : 0.f;
        __syncthreads();
        if (tid < 64) ss[tid] = si;
        __syncthreads();
        if (tid < 64) {
            int rank = 0;
            for (int j = 0; j < 64; j++) {
                float sj = ss[j];
                rank += (sj > si) || (sj == si && j < tid);
            }
            sc[SCOREO + bid * 64 + tid] = si;
            if (rank < KSEL) ((int*)(sc + PERMO))[bid * KSEL + rank] = tid;
        }
    }
    gsync(14);

    // ---- B15: outputs ----
    if (bid < NBAT) {
        float* Aws = sm;           // [64][65]
        float* Sp  = sm + 4160;    // [64][53]
        float* Ms  = sm + 7552;    // [64][53]
        int*   idx = (int*)(sm + 10944);
        const int* perm = (const int*)(sc + PERMO);
        const float* Ab = sc + AWO + (size_t)bid * 4096;
        for (int i = tid; i < 4096; i += NTHR) Aws[(i >> 6) * 65 + (i & 63)] = Ab[i];
        if (tid < KSEL) idx[tid] = perm[bid * KSEL + tid];
        __syncthreads();
        const float* Sb = sc + SO + (size_t)bid * 4096;
        for (int i = tid; i < 64 * KSEL; i += NTHR) {
            int r = i / KSEL, j = i % KSEL;
            Sp[r * 53 + j] = Sb[r * 64 + idx[j]];
        }
        __syncthreads();
        for (int i = tid; i < 64 * KSEL; i += NTHR) {
            int r = i / KSEL, j = i % KSEL;
            float acc = 0.f;
            #pragma unroll 8
            for (int c = 0; c < 64; c++) acc += Aws[r * 65 + c] * Sp[c * 53 + j];
            Ms[r * 53 + j] = acc;
        }
        __syncthreads();
        for (int i = tid; i < KSEL * KSEL; i += NTHR) {
            int ii = i / KSEL, j = i % KSEL;
            float v;
            if (ii == j) v = 1.f;
            else {
                v = 0.f;
                #pragma unroll 8
                for (int r = 0; r < 64; r++) v += Sp[r * 53 + ii] * Ms[r * 53 + j];
            }
            long long gi = (long long)bid * KSEL + ii;
            out[O_A2 + gi * NKEEP + bid * KSEL + j] = v;
        }
    } else {
        const int* perm = (const int*)(sc + PERMO);
        for (int t = (bid - NBAT) * NTHR + tid; t < NKEEP * HDIM; t += (NBLK - NBAT) * NTHR) {
            int j = t >> 7, k = t & 127;
            int b = j / KSEL;
            int pg = b * 64 + perm[j];
            out[t] = x[(size_t)pg * 128 + k] * sc[SCOREO + pg];
            if (k == 0) {
                out[O_BAT + j]  = (float)b;
                out[O_PERM + j] = (float)pg;
            }
        }
    }
}

extern "C" void kernel_launch(void* const* d_in, const int* in_sizes, int n_in,
                              void* d_out, int out_size) {
    const float* x   = (const float*)d_in[0];
    const int*   ei  = (const int*)d_in[1];
    const float* ew  = (const float*)d_in[2];
    const float* tgt = (const float*)d_in[3];
    const float* Wk  = (const float*)d_in[5];
    const float* W1  = (const float*)d_in[6];
    const float* W2  = (const float*)d_in[7];
    const float* W3  = (const float*)d_in[8];
    const float* lW  = (const float*)d_in[9];
    cudaFuncSetAttribute(mega, cudaFuncAttributeMaxDynamicSharedMemorySize,
                         DSMEM_FLOATS * sizeof(float));
    mega<<<NBLK, NTHR, DSMEM_FLOATS * sizeof(float)>>>(x, ei, ew, tgt, Wk, W1, W2, W3, lW,
                                                       (float*)d_out);
}

// round 17
// speedup vs baseline: 1.4377x; 1.2411x over previous
#include <cuda_runtime.h>
#include <mma.h>
using namespace nvcuda;

// ---------------- problem constants ----------------
#define NTOT 4096
#define HDIM 128
#define NBAT 64
#define NEDG 131072
#define KSEL 52
#define NKEEP 3328
#define NBLK 128           // (batch, head) persistent blocks, 1 CTA/SM
#define NTHR 512
#define GSTR (NBLK * NTHR)
#define SMF  50880         // dynamic smem floats (203520 B)

// output layout (float32 flat): x_out, A2, batch_out, perm
#define O_A2   425984LL
#define O_BAT  11501568LL
#define O_PERM 11504896LL

// scratch offsets (floats); pair tensors: hi plane then lo plane
#define WMP 0LL          // combined W1: 4 x 384 x 256 (lo +393216)
#define WKP 786432LL     // Wk (lo +65536)
#define W2P 917504LL     // W2 (lo +131072)
#define LWP 1179648LL    // lin_W (lo +32768)
#define XP  1245184LL    // x (lo +524288)
#define TGP 2293760LL    // target (lo +8192)
#define XQP 2310144LL    // per-batch x_q/x_q2 pair: b*16384 (lo +8192)
#define XCP 3358720LL    // per-batch x_c pair: b*16384 (lo +8192)
#define M2P 4407296LL    // per-batch M2 pair: b*8192 (lo +4096)
#define FO  4931584LL    // f values: kidx*4096 + b*64
#define AWO 4947968LL
#define CNTO 5210112LL
#define DEGO 5472256LL
#define SO  5476352LL
#define SCOREO 5738496LL
#define PERMO 5742592LL
#define SCRATCH_TOTAL 5746688LL

__device__ float g_scratch[SCRATCH_TOTAL];
__device__ unsigned g_bar[4 * 32];
__device__ unsigned g_flag[NBAT * 4];

__device__ __forceinline__ float lrelu(float v) { return v >= 0.f ? v : 0.01f * v; }

__device__ __forceinline__ void fsplit(float v, float& h, float& l) {
    h = wmma::__float_to_tf32(v);
    l = wmma::__float_to_tf32(v - h);
}

// monotonic-ticket grid barrier; gpu fences flush L1D
__device__ __forceinline__ void gsync(int i) {
    __syncthreads();
    if (threadIdx.x == 0) {
        __threadfence();
        unsigned t = atomicAdd(&g_bar[i * 32], 1u);
        unsigned target = (t / NBLK + 1u) * NBLK;
        while ((int)(*(volatile unsigned*)&g_bar[i * 32] - target) < 0) { __nanosleep(64); }
        __threadfence();
    }
    __syncthreads();
}

// pairwise release/acquire flags (zeroed in P0)
__device__ __forceinline__ void signalf(int idx) {
    __syncthreads();
    if (threadIdx.x == 0) { __threadfence(); atomicExch(&g_flag[idx], 1u); }
}
__device__ __forceinline__ void waitf(int idx) {
    __syncthreads();
    if (threadIdx.x == 0) {
        while (atomicAdd(&g_flag[idx], 0u) == 0u) __nanosleep(64);
        __threadfence();
    }
    __syncthreads();
}

typedef wmma::fragment<wmma::matrix_a, 16, 16, 8, wmma::precision::tf32, wmma::row_major> FragA;
typedef wmma::fragment<wmma::matrix_b, 16, 16, 8, wmma::precision::tf32, wmma::row_major> FragB;
typedef wmma::fragment<wmma::accumulator, 16, 16, 8, float> FragC;

template <int NF>
__device__ __forceinline__ void fz(FragC* M, FragC* E) {
    #pragma unroll
    for (int t = 0; t < NF; t++) { wmma::fill_fragment(M[t], 0.f); wmma::fill_fragment(E[t], 0.f); }
}

// combine M+E (opt lrelu), split, store hi/lo with stride ld
template <int NF>
__device__ void store_split(FragC* M, FragC* E, float* dh, float* dl, int ld, bool act) {
    int w = threadIdx.x >> 5, wr = w >> 2, wc = w & 3;
    #pragma unroll
    for (int t = 0; t < NF; t++) {
        FragC lo;
        #pragma unroll
        for (int e = 0; e < M[t].num_elements; e++) {
            float v = M[t].x[e] + E[t].x[e];
            if (act) v = lrelu(v);
            fsplit(v, M[t].x[e], lo.x[e]);
        }
        wmma::store_matrix_sync(dh + (wr * 16) * ld + wc * NF * 16 + t * 16, M[t], ld, wmma::mem_row_major);
        wmma::store_matrix_sync(dl + (wr * 16) * ld + wc * NF * 16 + t * 16, lo, ld, wmma::mem_row_major);
    }
}

template <int NF>
__device__ void store_f32(FragC* M, FragC* E, float* d, int ld, bool act) {
    int w = threadIdx.x >> 5, wr = w >> 2, wc = w & 3;
    #pragma unroll
    for (int t = 0; t < NF; t++) {
        #pragma unroll
        for (int e = 0; e < M[t].num_elements; e++) {
            float v = M[t].x[e] + E[t].x[e];
            M[t].x[e] = act ? lrelu(v) : v;
        }
        wmma::store_matrix_sync(d + (wr * 16) * ld + wc * NF * 16 + t * 16, M[t], ld, wmma::mem_row_major);
    }
}

// 64xN += A(64xK, smem pair, stride lda) @ W(KxN, global pair); weight chunks staged [32][N+4]
template <int NF>
__device__ void gemm_block(const float* Ah, const float* Al, int lda, int K,
                           const float* __restrict__ Wh, const float* __restrict__ Wl,
                           float* WSh, float* WSl, FragC* accM, FragC* accE) {
    const int N = NF * 64, LDW = N + 4, Q = N / 4;
    int tid = threadIdx.x, w = tid >> 5, wr = w >> 2, wc = w & 3;
    for (int k0 = 0; k0 < K; k0 += 32) {
        for (int i = tid; i < 8 * N; i += NTHR) {
            int r = i / Q, c4 = (i % Q) * 4;
            *(float4*)&WSh[r * LDW + c4] = *(const float4*)(Wh + (size_t)(k0 + r) * N + c4);
            *(float4*)&WSl[r * LDW + c4] = *(const float4*)(Wl + (size_t)(k0 + r) * N + c4);
        }
        __syncthreads();
        #pragma unroll
        for (int kk = 0; kk < 32; kk += 8) {
            FragA ah, al;
            wmma::load_matrix_sync(ah, Ah + (wr * 16) * lda + k0 + kk, lda);
            wmma::load_matrix_sync(al, Al + (wr * 16) * lda + k0 + kk, lda);
            #pragma unroll
            for (int t = 0; t < NF; t++) {
                FragB bh, bl;
                wmma::load_matrix_sync(bh, WSh + kk * LDW + wc * NF * 16 + t * 16, LDW);
                wmma::load_matrix_sync(bl, WSl + kk * LDW + wc * NF * 16 + t * 16, LDW);
                wmma::mma_sync(accM[t], ah, bh, accM[t]);
                wmma::mma_sync(accE[t], al, bh, accE[t]);
                wmma::mma_sync(accE[t], ah, bl, accE[t]);
            }
        }
        __syncthreads();
    }
}

// out(64x128) = A(64x64, smem stride 68 pair) @ B(64x128, smem stride 132 pair)
__device__ void gemm68(const float* Ah, const float* Al, const float* Bh, const float* Bl,
                       float* oh, float* ol, int ldo) {
    int w = threadIdx.x >> 5, wr = w >> 2, wc = w & 3;
    FragC M[2], E[2]; fz<2>(M, E);
    #pragma unroll
    for (int kk = 0; kk < 64; kk += 8) {
        FragA ah, al;
        wmma::load_matrix_sync(ah, Ah + (wr * 16) * 68 + kk, 68);
        wmma::load_matrix_sync(al, Al + (wr * 16) * 68 + kk, 68);
        #pragma unroll
        for (int t = 0; t < 2; t++) {
            FragB bh, bl;
            wmma::load_matrix_sync(bh, Bh + kk * 132 + wc * 32 + t * 16, 132);
            wmma::load_matrix_sync(bl, Bl + kk * 132 + wc * 32 + t * 16, 132);
            wmma::mma_sync(M[t], ah, bh, M[t]);
            wmma::mma_sync(E[t], al, bh, E[t]);
            wmma::mma_sync(E[t], ah, bl, E[t]);
        }
    }
    __syncthreads();
    store_split<2>(M, E, oh, ol, ldo, false);
}

// [64][128] global pair -> [64][132] smem pair
__device__ void stage_pair(const float* gh, const float* gl, float* sh, float* sl) {
    for (int i = threadIdx.x; i < 2048; i += NTHR) {
        int r = i >> 5, c4 = (i & 31) << 2;
        *(float4*)&sh[r * 132 + c4] = *(const float4*)(gh + r * 128 + c4);
        *(float4*)&sl[r * 132 + c4] = *(const float4*)(gl + r * 128 + c4);
    }
}

// [64][64] global pair -> [64][68] smem pair
__device__ void stage_m2(const float* gh, const float* gl, float* sh, float* sl) {
    for (int i = threadIdx.x; i < 1024; i += NTHR) {
        int r = i >> 4, c4 = (i & 15) << 2;
        *(float4*)&sh[r * 68 + c4] = *(const float4*)(gh + r * 64 + c4);
        *(float4*)&sl[r * 68 + c4] = *(const float4*)(gl + r * 64 + c4);
    }
}

// M2 = Aw^T @ Aw^T (64x64), split pair to global
__device__ void m2build(const float* __restrict__ Aw, float* Ph, float* Pl, float* sm) {
    float* Th = sm; float* Tl = sm + 8448;
    int tid = threadIdx.x;
    for (int i = tid; i < 4096; i += NTHR) {
        float hh, hl; fsplit(Aw[i], hh, hl);
        int r = i >> 6, c = i & 63;
        Th[c * 68 + r] = hh; Tl[c * 68 + r] = hl;
    }
    __syncthreads();
    int w = tid >> 5, wr = w >> 2, wc = w & 3;
    FragC M, E;
    wmma::fill_fragment(M, 0.f); wmma::fill_fragment(E, 0.f);
    #pragma unroll
    for (int kk = 0; kk < 64; kk += 8) {
        FragA ah, al;
        wmma::load_matrix_sync(ah, Th + (wr * 16) * 68 + kk, 68);
        wmma::load_matrix_sync(al, Tl + (wr * 16) * 68 + kk, 68);
        FragB bh, bl;
        wmma::load_matrix_sync(bh, Th + kk * 68 + wc * 16, 68);
        wmma::load_matrix_sync(bl, Tl + kk * 68 + wc * 16, 68);
        wmma::mma_sync(M, ah, bh, M);
        wmma::mma_sync(E, al, bh, E);
        wmma::mma_sync(E, ah, bl, E);
    }
    FragC lo;
    #pragma unroll
    for (int e = 0; e < M.num_elements; e++) { float v = M.x[e] + E.x[e]; fsplit(v, M.x[e], lo.x[e]); }
    wmma::store_matrix_sync(Ph + (wr * 16) * 64 + wc * 16, M, 64, wmma::mem_row_major);
    wmma::store_matrix_sync(Pl + (wr * 16) * 64 + wc * 16, lo, 64, wmma::mem_row_major);
    __syncthreads();
}

// ---------------- full attention MLP for one (batch, head), activations in smem ----
__device__ void mlp(float* sm, float* sc, int b, int kidx,
                    const float* kvh, const float* kvl,
                    const float* qh, const float* ql, int qtar,
                    const float* __restrict__ W3g) {
    float* R1h = sm;          float* R1l = sm + 8448;
    float* R2h = sm + 16896;  float* R2l = sm + 25344;
    float* R3a = sm + 33792;  float* R3b = sm + 42240;
    float* RED = sm + 50688;
    int tid = threadIdx.x;
    // kv -> R1; a = kv @ Wk -> pair R2
    stage_pair(kvh, kvl, R1h, R1l);
    __syncthreads();
    {
        FragC aM[2], aE[2]; fz<2>(aM, aE);
        gemm_block<2>(R1h, R1l, 132, 128,
                      sc + WKP + (size_t)kidx * 16384, sc + WKP + 65536 + (size_t)kidx * 16384,
                      R3a, R3b, aM, aE);
        store_split<2>(aM, aE, R2h, R2l, 132, false);
    }
    __syncthreads();
    // q -> R1
    if (qtar) {
        for (int i = tid; i < 2048; i += NTHR) {
            int r = i >> 5, c4 = (i & 31) << 2;
            *(float4*)&R1h[r * 132 + c4] = *(const float4*)(qh + c4);
            *(float4*)&R1l[r * 132 + c4] = *(const float4*)(ql + c4);
        }
    } else stage_pair(qh, ql, R1h, R1l);
    __syncthreads();
    // h1 = lrelu(a@Wm0 + q@Wm1 + aq@Wm2), K=128 each, accumulated
    FragC hM[4], hE[4]; fz<4>(hM, hE);
    const float* wm = sc + WMP + (size_t)kidx * 98304;
    const float* wml = wm + 393216;
    gemm_block<4>(R2h, R2l, 132, 128, wm,         wml,         R3a, R3b, hM, hE);
    gemm_block<4>(R1h, R1l, 132, 128, wm + 32768, wml + 32768, R3a, R3b, hM, hE);
    for (int i = tid; i < 8192; i += NTHR) {   // aq = a*q -> R1 (in place)
        int r = i >> 7, c = i & 127;
        float av = R2h[r * 132 + c] + R2l[r * 132 + c];
        float qv = R1h[r * 132 + c] + R1l[r * 132 + c];
        fsplit(av * qv, R1h[r * 132 + c], R1l[r * 132 + c]);
    }
    __syncthreads();
    gemm_block<4>(R1h, R1l, 132, 128, wm + 65536, wml + 65536, R3a, R3b, hM, hE);
    store_split<4>(hM, hE, sm, sm + 16896, 260, true);   // h1 pair, stride 260
    __syncthreads();
    // h2 = lrelu(h1 @ W2) -> fp32 R3a
    {
        FragC cM[2], cE[2]; fz<2>(cM, cE);
        const float* w2 = sc + W2P + (size_t)kidx * 32768;
        gemm_block<2>(sm, sm + 16896, 260, 256, w2, w2 + 131072, R3a, R3b, cM, cE);
        store_f32<2>(cM, cE, R3a, 132, true);
    }
    __syncthreads();
    // f = segment-softmax(lrelu(h2 . W3))
    if (tid < 128) RED[64 + tid] = W3g[kidx * 128 + tid];
    __syncthreads();
    float v = 0.f;
    if (tid < 64) {
        float d = 0.f;
        #pragma unroll 8
        for (int k = 0; k < 128; k++) d += R3a[tid * 132 + k] * RED[64 + k];
        v = lrelu(d);
        RED[tid] = v;
    }
    __syncthreads();
    for (int off = 32; off > 0; off >>= 1) {
        if (tid < off) RED[tid] = fmaxf(RED[tid], RED[tid + off]);
        __syncthreads();
    }
    float m = RED[0];
    __syncthreads();
    float e = 0.f;
    if (tid < 64) { e = expf(v - m); RED[tid] = e; }
    __syncthreads();
    for (int off = 32; off > 0; off >>= 1) {
        if (tid < off) RED[tid] += RED[tid + off];
        __syncthreads();
    }
    if (tid < 64) sc[FO + (size_t)kidx * 4096 + b * 64 + tid] = e / RED[0];
    __syncthreads();
}

// ==================== megakernel ====================
__global__ void __launch_bounds__(NTHR, 1)
mega(const float* __restrict__ x, const int* __restrict__ ei,
     const float* __restrict__ ew, const float* __restrict__ tgt,
     const float* __restrict__ Wk, const float* __restrict__ W1,
     const float* __restrict__ W2, const float* __restrict__ W3,
     const float* __restrict__ lW, float* __restrict__ out) {
    extern __shared__ __align__(16) float sm[];
    float* sc = g_scratch;
    int bid = blockIdx.x, tid = threadIdx.x;
    int gth = bid * NTHR + tid;
    float* R1h = sm;          float* R1l = sm + 8448;
    float* R2h = sm + 16896;  float* R2l = sm + 25344;
    float* R3a = sm + 33792;  float* R3b = sm + 42240;
    float* RED = sm + 50688;

    // ---- P0: build planes; zero Aw/cnt/deg + A2 + flags ----
    for (int i = gth; i < 4 * 384 * 256; i += GSTR) {   // Wm = [Wa+Wc; Wb-Wc; Wd]
        int c = i & 255, r = (i >> 8) % 384, h = i / (384 * 256);
        const float* Wh = W1 + (size_t)h * 512 * 256;
        float v;
        if (r < 128)      v = Wh[r * 256 + c] + Wh[(256 + r) * 256 + c];
        else if (r < 256) v = Wh[r * 256 + c] - Wh[(r + 128) * 256 + c];
        else              v = Wh[(r + 128) * 256 + c];
        fsplit(v, sc[WMP + i], sc[WMP + 393216 + i]);
    }
    for (int i = gth; i < 4 * 16384; i += GSTR)  fsplit(Wk[i], sc[WKP + i], sc[WKP + 65536 + i]);
    for (int i = gth; i < 4 * 32768; i += GSTR)  fsplit(W2[i], sc[W2P + i], sc[W2P + 131072 + i]);
    for (int i = gth; i < 2 * 16384; i += GSTR)  fsplit(lW[i], sc[LWP + i], sc[LWP + 32768 + i]);
    for (int i = gth; i < NTOT * 128; i += GSTR) fsplit(x[i],  sc[XP + i],  sc[XP + 524288 + i]);
    for (int i = gth; i < NBAT * 128; i += GSTR) fsplit(tgt[i], sc[TGP + i], sc[TGP + 8192 + i]);
    {
        float4 z = make_float4(0.f, 0.f, 0.f, 0.f);
        float4* p = (float4*)(sc + AWO);
        for (int i = gth; i < 528384 / 4; i += GSTR) p[i] = z;
        float4* p2 = (float4*)(out + O_A2);
        for (int i = gth; i < (NKEEP * NKEEP) / 4; i += GSTR) p2[i] = z;
        if (gth < NBAT * 4) g_flag[gth] = 0u;
    }
    gsync(0);

    // ---- P1: degree ----
    for (int e = gth; e < NEDG + NTOT; e += GSTR) {
        if (e < NEDG) atomicAdd(&sc[DEGO + ei[NEDG + e]], ew[e]);
        else          atomicAdd(&sc[DEGO + e - NEDG], 1.0f);
    }
    gsync(1);

    // ---- P2: dense adjacency with inline dinv ----
    for (int e = gth; e < NEDG + NTOT; e += GSTR) {
        int r, c; float wv;
        if (e < NEDG) { r = ei[e]; c = ei[NEDG + e]; wv = ew[e]; }
        else          { r = c = e - NEDG; wv = 1.f; }
        float dr = sc[DEGO + r], dc = sc[DEGO + c];
        float ir = dr > 0.f ? rsqrtf(fmaxf(dr, 1e-12f)) : 0.f;
        float ic = dc > 0.f ? rsqrtf(fmaxf(dc, 1e-12f)) : 0.f;
        int o = ((r >> 6) << 12) + ((r & 63) << 6) + (c & 63);
        atomicAdd(&sc[AWO + o], ir * wv * ic);
        atomicAdd(&sc[CNTO + o], 1.f);
    }
    gsync(2);

    // ---- per-batch pipelines: bid = 2*b + role ----
    int b = bid >> 1, role = bid & 1;
    int fb = b * 4;
    float* m2h = sc + M2P + (size_t)b * 8192;
    float* m2l = m2h + 4096;
    const float* xbh = sc + XP + (size_t)b * 8192;
    const float* xbl = sc + XP + 524288 + (size_t)b * 8192;
    float* xqh = sc + XQP + (size_t)b * 16384;  float* xql = xqh + 8192;
    float* xch = sc + XCP + (size_t)b * 16384;  float* xcl = xch + 8192;
    const int* perm = (const int*)(sc + PERMO);

    if (role == 0) {
        // M2 = Aw^T Aw^T; x_q = M2 @ x
        m2build(sc + AWO + (size_t)b * 4096, m2h, m2l, sm);
        stage_m2(m2h, m2l, R1h, R1l);
        stage_pair(xbh, xbl, R2h, R2l);
        __syncthreads();
        gemm68(R1h, R1l, R2h, R2l, xqh, xql, 128);
        __syncthreads();
        // f1 = att(x, x_q)
        mlp(sm, sc, b, 0, xbh, xbl, xqh, xql, 0, W3);
        // wait f2; build S (+S^T in smem), agg, x_c
        waitf(fb + 0);
        if (tid < 64) RED[tid] = sc[FO + 4096 + b * 64 + tid];   // f2 values
        __syncthreads();
        if (tid < 64) {
            int c = tid;
            float f1c = sc[FO + b * 64 + c];
            const float* Cb = sc + CNTO + (size_t)b * 4096;
            float* Sb = sc + SO + (size_t)b * 4096;
            float m = -1e30f;
            for (int r = 0; r < 64; r++) m = fmaxf(m, lrelu(f1c + RED[r]));
            float d = 0.f;
            float col[64];
            for (int r = 0; r < 64; r++) {
                float val = lrelu(f1c + RED[r]);
                float e = Cb[r * 64 + c] * expf(val - m);
                col[r] = e; d += e;
            }
            float inv = 1.f / d;
            for (int r = 0; r < 64; r++) {
                float s = col[r] * inv;
                Sb[r * 64 + c] = s;
                float hh, hl; fsplit(s, hh, hl);
                R1h[c * 68 + r] = hh;   // S^T pair into R1
                R1l[c * 68 + r] = hl;
            }
        }
        __syncthreads();
        stage_pair(xbh, xbl, R2h, R2l);
        __syncthreads();
        gemm68(R1h, R1l, R2h, R2l, R1h, R1l, 132);   // agg pair -> R1 (stride 132)
        __syncthreads();
        // x_c = 0.5*(lrelu(x+agg@W0)+lrelu(x+agg@W1))
        {
            FragC M[2], E[2]; fz<2>(M, E);
            gemm_block<2>(R1h, R1l, 132, 128, sc + LWP, sc + LWP + 32768, R3a, R3b, M, E);
            store_f32<2>(M, E, R2h, 132, false);     // t0 -> R2h
        }
        __syncthreads();
        {
            FragC M[2], E[2]; fz<2>(M, E);
            gemm_block<2>(R1h, R1l, 132, 128, sc + LWP + 16384, sc + LWP + 49152, R3a, R3b, M, E);
            store_f32<2>(M, E, R3a, 132, false);     // t1 -> R3a
        }
        __syncthreads();
        for (int i = tid; i < 8192; i += NTHR) {
            int r = i >> 7, c = i & 127;
            float xv = x[(size_t)(b * 64 + r) * 128 + c];
            float v = 0.5f * (lrelu(xv + R2h[r * 132 + c]) + lrelu(xv + R3a[r * 132 + c]));
            float hh, hl; fsplit(v, hh, hl);
            xch[r * 128 + c] = hh; xcl[r * 128 + c] = hl;
        }
        signalf(fb + 1);
        // x_q2 = M2 @ x_c
        stage_m2(m2h, m2l, R1h, R1l);
        stage_pair(xch, xcl, R2h, R2l);
        __syncthreads();
        gemm68(R1h, R1l, R2h, R2l, xqh, xql, 128);
        __syncthreads();
        // g1 = att(x_c, x_q2)
        mlp(sm, sc, b, 2, xch, xcl, xqh, xql, 0, W3);
        // wait g2; score softmax + rank top-k
        waitf(fb + 2);
        float si = 0.f;
        {
            float v = 0.f;
            if (tid < 64) {
                v = sc[FO + 2 * 4096 + b * 64 + tid] + sc[FO + 3 * 4096 + b * 64 + tid];
                RED[tid] = v;
            }
            __syncthreads();
            for (int off = 32; off > 0; off >>= 1) {
                if (tid < off) RED[tid] = fmaxf(RED[tid], RED[tid + off]);
                __syncthreads();
            }
            float m = RED[0];
            __syncthreads();
            float e = 0.f;
            if (tid < 64) { e = expf(v - m); RED[tid] = e; }
            __syncthreads();
            for (int off = 32; off > 0; off >>= 1) {
                if (tid < off) RED[tid] += RED[tid + off];
                __syncthreads();
            }
            if (tid < 64) { si = e / RED[0]; }
            __syncthreads();
            if (tid < 64) RED[64 + tid] = si;
            __syncthreads();
            if (tid < 64) {
                int rank = 0;
                for (int j = 0; j < 64; j++) {
                    float sj = RED[64 + j];
                    rank += (sj > si) || (sj == si && j < tid);
                }
                sc[SCOREO + b * 64 + tid] = si;
                if (rank < KSEL) ((int*)(sc + PERMO))[b * KSEL + rank] = tid;
            }
        }
        signalf(fb + 3);
        // A2 diagonal block: Sp^T (Aw Sp), diag=1
        {
            float* Aws = R1h;           // [64][65]
            float* Sp  = R1l;           // [64][53]
            float* Ms  = R2h;           // [64][53]
            int*   idx = (int*)(RED + 128);
            const float* Ab = sc + AWO + (size_t)b * 4096;
            for (int i = tid; i < 4096; i += NTHR) Aws[(i >> 6) * 65 + (i & 63)] = Ab[i];
            if (tid < KSEL) idx[tid] = ((int*)(sc + PERMO))[b * KSEL + tid];
            __syncthreads();
            const float* Sb = sc + SO + (size_t)b * 4096;
            for (int i = tid; i < 64 * KSEL; i += NTHR) {
                int r = i / KSEL, j = i % KSEL;
                Sp[r * 53 + j] = Sb[r * 64 + idx[j]];
            }
            __syncthreads();
            for (int i = tid; i < 64 * KSEL; i += NTHR) {
                int r = i / KSEL, j = i % KSEL;
                float acc = 0.f;
                #pragma unroll 8
                for (int c = 0; c < 64; c++) acc += Aws[r * 65 + c] * Sp[c * 53 + j];
                Ms[r * 53 + j] = acc;
            }
            __syncthreads();
            for (int i = tid; i < KSEL * KSEL; i += NTHR) {
                int ii = i / KSEL, j = i % KSEL;
                float v;
                if (ii == j) v = 1.f;
                else {
                    v = 0.f;
                    #pragma unroll 8
                    for (int r = 0; r < 64; r++) v += Sp[r * 53 + ii] * Ms[r * 53 + j];
                }
                long long gi = (long long)b * KSEL + ii;
                out[O_A2 + gi * NKEEP + b * KSEL + j] = v;
            }
        }
    } else {
        // f2 = att(x, qt)
        mlp(sm, sc, b, 1, xbh, xbl, sc + TGP + b * 128, sc + TGP + 8192 + b * 128, 1, W3);
        signalf(fb + 0);
        // g2 = att(x_c, qt)
        waitf(fb + 1);
        mlp(sm, sc, b, 3, xch, xcl, sc + TGP + b * 128, sc + TGP + 8192 + b * 128, 1, W3);
        signalf(fb + 2);
        // x_out / batch_out / perm for batch b
        waitf(fb + 3);
        for (int t = tid; t < KSEL * 128; t += NTHR) {
            int j = t >> 7, k = t & 127;
            int jg = b * KSEL + j;
            int pg = b * 64 + perm[jg];
            out[(size_t)jg * 128 + k] = x[(size_t)pg * 128 + k] * sc[SCOREO + pg];
            if (k == 0) {
                out[O_BAT + jg]  = (float)b;
                out[O_PERM + jg] = (float)pg;
            }
        }
    }
}

extern "C" void kernel_launch(void* const* d_in, const int* in_sizes, int n_in,
                              void* d_out, int out_size) {
    const float* x   = (const float*)d_in[0];
    const int*   ei  = (const int*)d_in[1];
    const float* ew  = (const float*)d_in[2];
    const float* tgt = (const float*)d_in[3];
    const float* Wk  = (const float*)d_in[5];
    const float* W1  = (const float*)d_in[6];
    const float* W2  = (const float*)d_in[7];
    const float* W3  = (const float*)d_in[8];
    const float* lW  = (const float*)d_in[9];
    cudaFuncSetAttribute(mega, cudaFuncAttributeMaxDynamicSharedMemorySize, SMF * sizeof(float));
    mega<<<NBLK, NTHR, SMF * sizeof(float)>>>(x, ei, ew, tgt, Wk, W1, W2, W3, lW, (float*)d_out);
}